// round 8
// baseline (speedup 1.0000x reference)
#include <cuda_runtime.h>
#include <cuda_bf16.h>
#include <math.h>
#include <stdint.h>

#define DIMS   2560
#define NH     32
#define HD     80
#define SEQ    2048
#define QKV_N  (3*DIMS)

// ---------------- scratch (static device globals; no runtime allocation) ----
__device__ float g_qkv [SEQ * QKV_N];          // [t][3*DIMS]  q|k|v (fp32)

__device__ __nv_bfloat16 g_xhi [SEQ * DIMS];
__device__ __nv_bfloat16 g_xlo [SEQ * DIMS];
__device__ __nv_bfloat16 g_w1hi[QKV_N * DIMS];
__device__ __nv_bfloat16 g_w1lo[QKV_N * DIMS];
__device__ __nv_bfloat16 g_w2hi[DIMS * DIMS];
__device__ __nv_bfloat16 g_w2lo[DIMS * DIMS];
__device__ __nv_bfloat16 g_ahi [SEQ * DIMS];   // attention out hi/lo (bf16)
__device__ __nv_bfloat16 g_alo [SEQ * DIMS];
__device__ __nv_bfloat16 g_qkvhi[SEQ * QKV_N]; // post-rope qkv hi/lo (bf16)
__device__ __nv_bfloat16 g_qkvlo[SEQ * QKV_N];

// ============================================================================
// fp32 -> bf16 hi/lo split conversion (vectorized, memory bound)
// ============================================================================
__global__ void cvt_hilo_kernel(const float* __restrict__ src,
                                __nv_bfloat16* __restrict__ hi,
                                __nv_bfloat16* __restrict__ lo, int n4)
{
    int i = blockIdx.x * blockDim.x + threadIdx.x;
    if (i >= n4) return;
    float4 v = ((const float4*)src)[i];
    union { __nv_bfloat16 b[4]; uint2 u; } H, L;
    H.b[0] = __float2bfloat16(v.x); L.b[0] = __float2bfloat16(v.x - __bfloat162float(H.b[0]));
    H.b[1] = __float2bfloat16(v.y); L.b[1] = __float2bfloat16(v.y - __bfloat162float(H.b[1]));
    H.b[2] = __float2bfloat16(v.z); L.b[2] = __float2bfloat16(v.z - __bfloat162float(H.b[2]));
    H.b[3] = __float2bfloat16(v.w); L.b[3] = __float2bfloat16(v.w - __bfloat162float(H.b[3]));
    ((uint2*)hi)[i] = H.u;
    ((uint2*)lo)[i] = L.u;
}

// ============================================================================
// PTX helpers (all baseline compute_103-safe: sm_80-era instructions)
// ============================================================================
__device__ __forceinline__ uint32_t smem_u32(const void* p){
    uint32_t a;
    asm("{ .reg .u64 t; cvta.to.shared.u64 t, %1; cvt.u32.u64 %0, t; }"
        : "=r"(a) : "l"(p));
    return a;
}
__device__ __forceinline__ void cp16(uint32_t dst, const void* src){
    asm volatile("cp.async.ca.shared.global [%0], [%1], 16;"
                 :: "r"(dst), "l"(src) : "memory");
}
__device__ __forceinline__ void cp_commit(){
    asm volatile("cp.async.commit_group;" ::: "memory");
}
template<int N> __device__ __forceinline__ void cp_wait(){
    asm volatile("cp.async.wait_group %0;" :: "n"(N) : "memory");
}
__device__ __forceinline__ void ldm_x4(uint32_t a, uint32_t& r0, uint32_t& r1,
                                       uint32_t& r2, uint32_t& r3){
    asm volatile("ldmatrix.sync.aligned.m8n8.x4.shared.b16 {%0,%1,%2,%3}, [%4];"
                 : "=r"(r0), "=r"(r1), "=r"(r2), "=r"(r3) : "r"(a));
}
__device__ __forceinline__ void ldm_x4_t(uint32_t a, uint32_t& r0, uint32_t& r1,
                                         uint32_t& r2, uint32_t& r3){
    asm volatile("ldmatrix.sync.aligned.m8n8.x4.trans.shared.b16 {%0,%1,%2,%3}, [%4];"
                 : "=r"(r0), "=r"(r1), "=r"(r2), "=r"(r3) : "r"(a));
}
__device__ __forceinline__ void mma_bf16(float* c, const uint32_t* a,
                                         uint32_t b0, uint32_t b1){
    asm volatile(
      "mma.sync.aligned.m16n8k16.row.col.f32.bf16.bf16.f32 "
      "{%0,%1,%2,%3}, {%4,%5,%6,%7}, {%8,%9}, {%0,%1,%2,%3};"
      : "+f"(c[0]), "+f"(c[1]), "+f"(c[2]), "+f"(c[3])
      : "r"(a[0]), "r"(a[1]), "r"(a[2]), "r"(a[3]), "r"(b0), "r"(b1));
}
__device__ __forceinline__ uint32_t pkbf(__nv_bfloat16 a, __nv_bfloat16 b){
    union { __nv_bfloat16 h[2]; uint32_t u; } t;
    t.h[0] = a; t.h[1] = b;
    return t.u;
}

// ============================================================================
// bf16x3 tensor-core GEMM:  C[M,N] = A[M,K] @ B[N,K]^T + bias
// CTA tile 128x128, 4 warps, warp tile 64x64, BK=32, cp.async double buffer.
// MMA issue is TERM-MAJOR so dependent accumulator reuse distance = 8 MMAs.
// ============================================================================
#define GBM 128
#define GBN 128
#define GBK 32
#define ROWP 40
#define TILE_B (128 * ROWP * 2)
#define STAGE_B (4 * TILE_B)
#define GM_SMEM (2 * STAGE_B)

__global__ __launch_bounds__(128, 2) void gemm_bf16x3(
    const __nv_bfloat16* __restrict__ Ahi, const __nv_bfloat16* __restrict__ Alo,
    const __nv_bfloat16* __restrict__ Bhi, const __nv_bfloat16* __restrict__ Blo,
    const float* __restrict__ bias, float* __restrict__ C,
    int M, int N, int K)
{
    extern __shared__ __align__(16) char smem[];
    const uint32_t sb = smem_u32(smem);

    const int tid  = threadIdx.x;
    const int w    = tid >> 5;
    const int lane = tid & 31;
    const int bm   = blockIdx.y * GBM;
    const int bn   = blockIdx.x * GBN;
    const int wm   = (w & 1) * 64;
    const int wn   = (w >> 1) * 64;

    const __nv_bfloat16* gA_hi = Ahi + (size_t)bm * K;
    const __nv_bfloat16* gA_lo = Alo + (size_t)bm * K;
    const __nv_bfloat16* gB_hi = Bhi + (size_t)bn * K;
    const __nv_bfloat16* gB_lo = Blo + (size_t)bn * K;

    auto load_stage = [&](int s, int k0){
        const uint32_t dstb = sb + s * STAGE_B;
        const __nv_bfloat16* srcs[4] = { gA_hi, gA_lo, gB_hi, gB_lo };
#pragma unroll
        for (int t = 0; t < 4; t++) {
            const __nv_bfloat16* g = srcs[t];
            const uint32_t db = dstb + t * TILE_B;
#pragma unroll
            for (int i = 0; i < 4; i++) {
                const int idx = i * 128 + tid;
                const int row = idx >> 2;
                const int kq  = idx & 3;
                cp16(db + row * 80 + kq * 16, g + (size_t)row * K + k0 + kq * 8);
            }
        }
        cp_commit();
    };

    float acc[4][8][4];
#pragma unroll
    for (int mt = 0; mt < 4; mt++)
#pragma unroll
        for (int nt = 0; nt < 8; nt++)
#pragma unroll
            for (int r = 0; r < 4; r++) acc[mt][nt][r] = 0.f;

    const int nchunks = K / GBK;
    load_stage(0, 0);

    const int a_row  = lane & 15;
    const int a_koff = (lane >> 4) << 3;
    const int b_row  = (lane & 7) + ((lane >> 4) << 3);
    const int b_koff = ((lane >> 3) & 1) << 3;

    for (int ic = 0; ic < nchunks; ic++) {
        if (ic + 1 < nchunks) load_stage((ic + 1) & 1, (ic + 1) * GBK);
        if (ic + 1 < nchunks) cp_wait<1>(); else cp_wait<0>();
        __syncthreads();

        const uint32_t st = sb + (ic & 1) * STAGE_B;
        const uint32_t sAhi = st;
        const uint32_t sAlo = st + TILE_B;
        const uint32_t sBhi = st + 2 * TILE_B;
        const uint32_t sBlo = st + 3 * TILE_B;

#pragma unroll
        for (int ks = 0; ks < 2; ks++) {
            const int kb = ks * 16;
            uint32_t ahi[4][4], alo[4][4];
#pragma unroll
            for (int mt = 0; mt < 4; mt++) {
                const uint32_t aoff =
                    (uint32_t)((wm + mt * 16 + a_row) * 80 + (kb + a_koff) * 2);
                ldm_x4(sAhi + aoff, ahi[mt][0], ahi[mt][1], ahi[mt][2], ahi[mt][3]);
                ldm_x4(sAlo + aoff, alo[mt][0], alo[mt][1], alo[mt][2], alo[mt][3]);
            }
#pragma unroll
            for (int np = 0; np < 4; np++) {
                const uint32_t boff =
                    (uint32_t)((wn + np * 16 + b_row) * 80 + (kb + b_koff) * 2);
                uint32_t bh0, bh1, bh2, bh3, bl0, bl1, bl2, bl3;
                ldm_x4(sBhi + boff, bh0, bh1, bh2, bh3);
                ldm_x4(sBlo + boff, bl0, bl1, bl2, bl3);
                // term hi*hi: 8 independent MMAs
#pragma unroll
                for (int mt = 0; mt < 4; mt++) {
                    mma_bf16(acc[mt][2*np],   ahi[mt], bh0, bh1);
                    mma_bf16(acc[mt][2*np+1], ahi[mt], bh2, bh3);
                }
                // term hi*lo
#pragma unroll
                for (int mt = 0; mt < 4; mt++) {
                    mma_bf16(acc[mt][2*np],   ahi[mt], bl0, bl1);
                    mma_bf16(acc[mt][2*np+1], ahi[mt], bl2, bl3);
                }
                // term lo*hi
#pragma unroll
                for (int mt = 0; mt < 4; mt++) {
                    mma_bf16(acc[mt][2*np],   alo[mt], bh0, bh1);
                    mma_bf16(acc[mt][2*np+1], alo[mt], bh2, bh3);
                }
            }
        }
        __syncthreads();
    }

#pragma unroll
    for (int mt = 0; mt < 4; mt++) {
        const int r0 = bm + wm + mt * 16 + (lane >> 2);
#pragma unroll
        for (int nt = 0; nt < 8; nt++) {
            const int col = bn + wn + nt * 8 + ((lane & 3) << 1);
            const float2 bv = *(const float2*)&bias[col];
            float2 v0 = { acc[mt][nt][0] + bv.x, acc[mt][nt][1] + bv.y };
            float2 v1 = { acc[mt][nt][2] + bv.x, acc[mt][nt][3] + bv.y };
            *(float2*)&C[(size_t)r0       * N + col] = v0;
            *(float2*)&C[(size_t)(r0 + 8) * N + col] = v1;
        }
    }
}

// ============================================================================
// RoPE on q and k (first 32 dims of each 80-dim head), in place (fp32).
// ============================================================================
__global__ void rope_kernel(float* __restrict__ qkv)
{
    int idx = blockIdx.x * blockDim.x + threadIdx.x;      // SEQ*NH*16 total
    if (idx >= SEQ * NH * 16) return;
    const int d = idx & 15;
    const int h = (idx >> 4) & 31;
    const int t = idx >> 9;

    const float freq  = __expf(-(float)d * 0.5756462732485115f); // ln(1e4)/16
    const float theta = (float)t * freq;
    float s, c;
    sincosf(theta, &s, &c);

    size_t base = (size_t)t * QKV_N + h * HD;
    {
        float x1 = qkv[base + d], x2 = qkv[base + d + 16];
        qkv[base + d]      = x1 * c - x2 * s;
        qkv[base + d + 16] = x1 * s + x2 * c;
    }
    base += DIMS;
    {
        float x1 = qkv[base + d], x2 = qkv[base + d + 16];
        qkv[base + d]      = x1 * c - x2 * s;
        qkv[base + d + 16] = x1 * s + x2 * c;
    }
}

// ============================================================================
// Tensor-core flash attention, causal, bf16x3, term-major MMA ordering.
// ============================================================================
#define AP     88
#define SQ_HI  0
#define SQ_LO  (64*AP)
#define SK_HI  (2*64*AP)
#define SK_LO  (3*64*AP)
#define SV_HI  (4*64*AP)
#define SV_LO  (5*64*AP)
#define ATT_SMEM (6*64*AP*2)   // 67584 bytes

__global__ __launch_bounds__(128, 2) void attn_tc(
    const __nv_bfloat16* __restrict__ qkvhi,
    const __nv_bfloat16* __restrict__ qkvlo,
    __nv_bfloat16* __restrict__ ohi,
    __nv_bfloat16* __restrict__ olo)
{
    extern __shared__ __align__(16) __nv_bfloat16 smA[];
    const uint32_t sb = smem_u32(smA);
    const int h = blockIdx.x, qb = blockIdx.y;
    const int tid = threadIdx.x, lane = tid & 31, w = tid >> 5;
    const int q0 = qb * 64;
    const float scale = 0.11180339887498949f;   // 1/sqrt(80)

    {
        const size_t off = (size_t)q0 * QKV_N + h * HD;
#pragma unroll
        for (int it = 0; it < 5; it++) {
            const int idx = it * 128 + tid;
            const int row = idx / 10, col = idx % 10;
            const size_t go = off + (size_t)row * QKV_N + col * 8;
            cp16(sb + (SQ_HI + row * AP) * 2 + col * 16, qkvhi + go);
            cp16(sb + (SQ_LO + row * AP) * 2 + col * 16, qkvlo + go);
        }
    }
    auto loadKV = [&](int kb){
        const size_t koff = (size_t)(kb * 64) * QKV_N + DIMS + h * HD;
#pragma unroll
        for (int it = 0; it < 5; it++) {
            const int idx = it * 128 + tid;
            const int row = idx / 10, col = idx % 10;
            const size_t gk = koff + (size_t)row * QKV_N + col * 8;
            const size_t gv = gk + DIMS;
            cp16(sb + (SK_HI + row * AP) * 2 + col * 16, qkvhi + gk);
            cp16(sb + (SK_LO + row * AP) * 2 + col * 16, qkvlo + gk);
            cp16(sb + (SV_HI + row * AP) * 2 + col * 16, qkvhi + gv);
            cp16(sb + (SV_LO + row * AP) * 2 + col * 16, qkvlo + gv);
        }
    };

    float of[10][4];
#pragma unroll
    for (int i = 0; i < 10; i++)
#pragma unroll
        for (int j = 0; j < 4; j++) of[i][j] = 0.f;
    float mA = -1e30f, mB = -1e30f, lA = 0.f, lB = 0.f;

    loadKV(0);
    cp_commit(); cp_wait<0>();
    __syncthreads();

    const int a_row  = lane & 15;
    const int a_k    = (lane >> 4) << 3;
    const int b_row  = (lane & 7) + ((lane >> 4) << 3);
    const int b_k    = ((lane >> 3) & 1) << 3;
    const int vk     = (lane & 7) + (((lane >> 3) & 1) << 3);
    const int vd     = (lane >> 4) << 3;
    const int clb    = 2 * (lane & 3);
    const int rl     = w * 16 + (lane >> 2);

    const int ntiles = qb + 1;
    for (int kb = 0; kb < ntiles; kb++) {
        float sf[8][4];
#pragma unroll
        for (int i = 0; i < 8; i++)
#pragma unroll
            for (int j = 0; j < 4; j++) sf[i][j] = 0.f;

#pragma unroll
        for (int kc = 0; kc < 5; kc++) {
            uint32_t ahi[4], alo[4];
            const uint32_t aoff = (uint32_t)((w * 16 + a_row) * AP + kc * 16 + a_k) * 2;
            ldm_x4(sb + SQ_HI * 2 + aoff, ahi[0], ahi[1], ahi[2], ahi[3]);
            ldm_x4(sb + SQ_LO * 2 + aoff, alo[0], alo[1], alo[2], alo[3]);
            uint32_t bh[4][4], bl[4][4];
#pragma unroll
            for (int bp = 0; bp < 4; bp++) {
                const uint32_t boff = (uint32_t)((bp * 16 + b_row) * AP + kc * 16 + b_k) * 2;
                ldm_x4(sb + SK_HI * 2 + boff, bh[bp][0], bh[bp][1], bh[bp][2], bh[bp][3]);
                ldm_x4(sb + SK_LO * 2 + boff, bl[bp][0], bl[bp][1], bl[bp][2], bl[bp][3]);
            }
            // term hi*hi (8 independent MMAs)
#pragma unroll
            for (int bp = 0; bp < 4; bp++) {
                mma_bf16(sf[2*bp],   ahi, bh[bp][0], bh[bp][1]);
                mma_bf16(sf[2*bp+1], ahi, bh[bp][2], bh[bp][3]);
            }
            // term hi*lo
#pragma unroll
            for (int bp = 0; bp < 4; bp++) {
                mma_bf16(sf[2*bp],   ahi, bl[bp][0], bl[bp][1]);
                mma_bf16(sf[2*bp+1], ahi, bl[bp][2], bl[bp][3]);
            }
            // term lo*hi
#pragma unroll
            for (int bp = 0; bp < 4; bp++) {
                mma_bf16(sf[2*bp],   alo, bh[bp][0], bh[bp][1]);
                mma_bf16(sf[2*bp+1], alo, bh[bp][2], bh[bp][3]);
            }
        }

        const bool diag = (kb == qb);
#pragma unroll
        for (int nt = 0; nt < 8; nt++) {
            const int c0 = nt * 8 + clb;
#pragma unroll
            for (int j = 0; j < 2; j++) {
                float vA = sf[nt][j]     * scale;
                float vB = sf[nt][2 + j] * scale;
                if (diag) {
                    if (c0 + j > rl)     vA = -1e30f;
                    if (c0 + j > rl + 8) vB = -1e30f;
                }
                sf[nt][j] = vA; sf[nt][2 + j] = vB;
            }
        }

        float mxA = -1e30f, mxB = -1e30f;
#pragma unroll
        for (int nt = 0; nt < 8; nt++) {
            mxA = fmaxf(mxA, fmaxf(sf[nt][0], sf[nt][1]));
            mxB = fmaxf(mxB, fmaxf(sf[nt][2], sf[nt][3]));
        }
        mxA = fmaxf(mxA, __shfl_xor_sync(0xffffffffu, mxA, 1));
        mxA = fmaxf(mxA, __shfl_xor_sync(0xffffffffu, mxA, 2));
        mxB = fmaxf(mxB, __shfl_xor_sync(0xffffffffu, mxB, 1));
        mxB = fmaxf(mxB, __shfl_xor_sync(0xffffffffu, mxB, 2));
        const float mnA = fmaxf(mA, mxA), mnB = fmaxf(mB, mxB);
        const float alphaA = __expf(mA - mnA), alphaB = __expf(mB - mnB);
        mA = mnA; mB = mnB;

        float sA = 0.f, sB = 0.f;
#pragma unroll
        for (int nt = 0; nt < 8; nt++) {
#pragma unroll
            for (int j = 0; j < 2; j++) {
                float pA = __expf(sf[nt][j]     - mnA);
                float pB = __expf(sf[nt][2 + j] - mnB);
                sf[nt][j] = pA; sf[nt][2 + j] = pB;
                sA += pA; sB += pB;
            }
        }
        sA += __shfl_xor_sync(0xffffffffu, sA, 1);
        sA += __shfl_xor_sync(0xffffffffu, sA, 2);
        sB += __shfl_xor_sync(0xffffffffu, sB, 1);
        sB += __shfl_xor_sync(0xffffffffu, sB, 2);
        lA = lA * alphaA + sA;
        lB = lB * alphaB + sB;
#pragma unroll
        for (int d = 0; d < 10; d++) {
            of[d][0] *= alphaA; of[d][1] *= alphaA;
            of[d][2] *= alphaB; of[d][3] *= alphaB;
        }

#pragma unroll
        for (int kc2 = 0; kc2 < 4; kc2++) {
            uint32_t phi[4], plo[4];
#pragma unroll
            for (int half = 0; half < 2; half++) {
                const int nt = 2 * kc2 + half;
                const float v0 = sf[nt][0], v1 = sf[nt][1];
                const float v2 = sf[nt][2], v3 = sf[nt][3];
                __nv_bfloat16 h0 = __float2bfloat16(v0), h1 = __float2bfloat16(v1);
                __nv_bfloat16 h2 = __float2bfloat16(v2), h3 = __float2bfloat16(v3);
                phi[half * 2 + 0] = pkbf(h0, h1);
                phi[half * 2 + 1] = pkbf(h2, h3);
                plo[half * 2 + 0] = pkbf(__float2bfloat16(v0 - __bfloat162float(h0)),
                                         __float2bfloat16(v1 - __bfloat162float(h1)));
                plo[half * 2 + 1] = pkbf(__float2bfloat16(v2 - __bfloat162float(h2)),
                                         __float2bfloat16(v3 - __bfloat162float(h3)));
            }
            uint32_t aH[4] = { phi[0], phi[1], phi[2], phi[3] };
            uint32_t aL[4] = { plo[0], plo[1], plo[2], plo[3] };
            uint32_t vh[5][4], vl[5][4];
#pragma unroll
            for (int dp = 0; dp < 5; dp++) {
                const uint32_t voff = (uint32_t)((kc2 * 16 + vk) * AP + dp * 16 + vd) * 2;
                ldm_x4_t(sb + SV_HI * 2 + voff, vh[dp][0], vh[dp][1], vh[dp][2], vh[dp][3]);
                ldm_x4_t(sb + SV_LO * 2 + voff, vl[dp][0], vl[dp][1], vl[dp][2], vl[dp][3]);
            }
            // term P_hi * V_hi (10 independent MMAs)
#pragma unroll
            for (int dp = 0; dp < 5; dp++) {
                mma_bf16(of[2*dp],   aH, vh[dp][0], vh[dp][1]);
                mma_bf16(of[2*dp+1], aH, vh[dp][2], vh[dp][3]);
            }
            // term P_hi * V_lo
#pragma unroll
            for (int dp = 0; dp < 5; dp++) {
                mma_bf16(of[2*dp],   aH, vl[dp][0], vl[dp][1]);
                mma_bf16(of[2*dp+1], aH, vl[dp][2], vl[dp][3]);
            }
            // term P_lo * V_hi
#pragma unroll
            for (int dp = 0; dp < 5; dp++) {
                mma_bf16(of[2*dp],   aL, vh[dp][0], vh[dp][1]);
                mma_bf16(of[2*dp+1], aL, vh[dp][2], vh[dp][3]);
            }
        }

        __syncthreads();
        if (kb + 1 < ntiles) {
            loadKV(kb + 1);
            cp_commit(); cp_wait<0>();
        }
        __syncthreads();
    }

    const float iA = 1.f / lA, iB = 1.f / lB;
    const int gA = q0 + w * 16 + (lane >> 2);
    const int colb = h * HD + clb;
#pragma unroll
    for (int nt = 0; nt < 10; nt++) {
        const int col = colb + nt * 8;
        float v0 = of[nt][0] * iA, v1 = of[nt][1] * iA;
        float v2 = of[nt][2] * iB, v3 = of[nt][3] * iB;
        __nv_bfloat16 h0 = __float2bfloat16(v0), h1 = __float2bfloat16(v1);
        __nv_bfloat16 h2 = __float2bfloat16(v2), h3 = __float2bfloat16(v3);
        *(uint32_t*)(ohi + (size_t)gA * DIMS + col)       = pkbf(h0, h1);
        *(uint32_t*)(ohi + (size_t)(gA + 8) * DIMS + col) = pkbf(h2, h3);
        *(uint32_t*)(olo + (size_t)gA * DIMS + col)       =
            pkbf(__float2bfloat16(v0 - __bfloat162float(h0)),
                 __float2bfloat16(v1 - __bfloat162float(h1)));
        *(uint32_t*)(olo + (size_t)(gA + 8) * DIMS + col) =
            pkbf(__float2bfloat16(v2 - __bfloat162float(h2)),
                 __float2bfloat16(v3 - __bfloat162float(h3)));
    }
}

// ============================================================================
extern "C" void kernel_launch(void* const* d_in, const int* in_sizes, int n_in,
                              void* d_out, int out_size)
{
    const float* x       = (const float*)d_in[0];
    const float* Wqkv_w  = (const float*)d_in[1];
    const float* Wqkv_b  = (const float*)d_in[2];
    const float* out_w   = (const float*)d_in[3];
    const float* out_b   = (const float*)d_in[4];
    // d_in[5] = mask: causal triu(-1e9), implemented structurally; unused.
    float* outp = (float*)d_out;

    float *qkv_ptr = nullptr;
    __nv_bfloat16 *xhi, *xlo, *w1hi, *w1lo, *w2hi, *w2lo, *ahi, *alo, *qvh, *qvl;
    cudaGetSymbolAddress((void**)&qkv_ptr, g_qkv);
    cudaGetSymbolAddress((void**)&xhi,  g_xhi);   cudaGetSymbolAddress((void**)&xlo,  g_xlo);
    cudaGetSymbolAddress((void**)&w1hi, g_w1hi);  cudaGetSymbolAddress((void**)&w1lo, g_w1lo);
    cudaGetSymbolAddress((void**)&w2hi, g_w2hi);  cudaGetSymbolAddress((void**)&w2lo, g_w2lo);
    cudaGetSymbolAddress((void**)&ahi,  g_ahi);   cudaGetSymbolAddress((void**)&alo,  g_alo);
    cudaGetSymbolAddress((void**)&qvh,  g_qkvhi); cudaGetSymbolAddress((void**)&qvl,  g_qkvlo);

    cudaFuncSetAttribute(gemm_bf16x3,
                         cudaFuncAttributeMaxDynamicSharedMemorySize, GM_SMEM);
    cudaFuncSetAttribute(attn_tc,
                         cudaFuncAttributeMaxDynamicSharedMemorySize, ATT_SMEM);

    // 0) split-precision conversions of x and weights
    {
        int n4 = (SEQ * DIMS) / 4;
        cvt_hilo_kernel<<<(n4 + 255) / 256, 256>>>(x, xhi, xlo, n4);
        n4 = (QKV_N * DIMS) / 4;
        cvt_hilo_kernel<<<(n4 + 255) / 256, 256>>>(Wqkv_w, w1hi, w1lo, n4);
        n4 = (DIMS * DIMS) / 4;
        cvt_hilo_kernel<<<(n4 + 255) / 256, 256>>>(out_w, w2hi, w2lo, n4);
    }
    // 1) QKV projection (bf16x3 tensor cores) -> fp32 qkv
    {
        dim3 grid(QKV_N / GBN, SEQ / GBM);
        gemm_bf16x3<<<grid, 128, GM_SMEM>>>(xhi, xlo, w1hi, w1lo,
                                            Wqkv_b, qkv_ptr, SEQ, QKV_N, DIMS);
    }
    // 2) RoPE on q,k (fp32, in place)
    {
        int total = SEQ * NH * 16;
        rope_kernel<<<(total + 255) / 256, 256>>>(qkv_ptr);
    }
    // 3) qkv -> bf16 hi/lo
    {
        int n4 = (SEQ * QKV_N) / 4;
        cvt_hilo_kernel<<<(n4 + 255) / 256, 256>>>(qkv_ptr, qvh, qvl, n4);
    }
    // 4) tensor-core causal flash attention -> bf16 hi/lo attn out
    {
        dim3 grid(NH, SEQ / 64);
        attn_tc<<<grid, 128, ATT_SMEM>>>(qvh, qvl, ahi, alo);
    }
    // 5) output projection (bf16x3 tensor cores)
    {
        dim3 grid(DIMS / GBN, SEQ / GBM);
        gemm_bf16x3<<<grid, 128, GM_SMEM>>>(ahi, alo, w2hi, w2lo,
                                            out_b, outp, SEQ, DIMS, DIMS);
    }
}

// round 9
// speedup vs baseline: 1.0528x; 1.0528x over previous
#include <cuda_runtime.h>
#include <cuda_bf16.h>
#include <math.h>
#include <stdint.h>

#define DIMS   2560
#define NH     32
#define HD     80
#define SEQ    2048
#define QKV_N  (3*DIMS)

// ---------------- scratch (static device globals; no runtime allocation) ----
__device__ __nv_bfloat16 g_xhi [SEQ * DIMS];
__device__ __nv_bfloat16 g_xlo [SEQ * DIMS];
__device__ __nv_bfloat16 g_w1hi[QKV_N * DIMS];
__device__ __nv_bfloat16 g_w1lo[QKV_N * DIMS];
__device__ __nv_bfloat16 g_w2hi[DIMS * DIMS];
__device__ __nv_bfloat16 g_w2lo[DIMS * DIMS];
__device__ __nv_bfloat16 g_ahi [SEQ * DIMS];   // attention out hi/lo (bf16)
__device__ __nv_bfloat16 g_alo [SEQ * DIMS];
__device__ __nv_bfloat16 g_qkvhi[SEQ * QKV_N]; // qkv hi/lo (bf16), rope applied
__device__ __nv_bfloat16 g_qkvlo[SEQ * QKV_N];

// ============================================================================
// fp32 -> bf16 hi/lo split conversion (vectorized, memory bound)
// ============================================================================
__global__ void cvt_hilo_kernel(const float* __restrict__ src,
                                __nv_bfloat16* __restrict__ hi,
                                __nv_bfloat16* __restrict__ lo, int n4)
{
    int i = blockIdx.x * blockDim.x + threadIdx.x;
    if (i >= n4) return;
    float4 v = ((const float4*)src)[i];
    union { __nv_bfloat16 b[4]; uint2 u; } H, L;
    H.b[0] = __float2bfloat16(v.x); L.b[0] = __float2bfloat16(v.x - __bfloat162float(H.b[0]));
    H.b[1] = __float2bfloat16(v.y); L.b[1] = __float2bfloat16(v.y - __bfloat162float(H.b[1]));
    H.b[2] = __float2bfloat16(v.z); L.b[2] = __float2bfloat16(v.z - __bfloat162float(H.b[2]));
    H.b[3] = __float2bfloat16(v.w); L.b[3] = __float2bfloat16(v.w - __bfloat162float(H.b[3]));
    ((uint2*)hi)[i] = H.u;
    ((uint2*)lo)[i] = L.u;
}

// ============================================================================
// PTX helpers (all baseline compute_103-safe: sm_80-era instructions)
// ============================================================================
__device__ __forceinline__ uint32_t smem_u32(const void* p){
    uint32_t a;
    asm("{ .reg .u64 t; cvta.to.shared.u64 t, %1; cvt.u32.u64 %0, t; }"
        : "=r"(a) : "l"(p));
    return a;
}
__device__ __forceinline__ void cp16(uint32_t dst, const void* src){
    asm volatile("cp.async.ca.shared.global [%0], [%1], 16;"
                 :: "r"(dst), "l"(src) : "memory");
}
__device__ __forceinline__ void cp_commit(){
    asm volatile("cp.async.commit_group;" ::: "memory");
}
template<int N> __device__ __forceinline__ void cp_wait(){
    asm volatile("cp.async.wait_group %0;" :: "n"(N) : "memory");
}
__device__ __forceinline__ void ldm_x4(uint32_t a, uint32_t& r0, uint32_t& r1,
                                       uint32_t& r2, uint32_t& r3){
    asm volatile("ldmatrix.sync.aligned.m8n8.x4.shared.b16 {%0,%1,%2,%3}, [%4];"
                 : "=r"(r0), "=r"(r1), "=r"(r2), "=r"(r3) : "r"(a));
}
__device__ __forceinline__ void ldm_x4_t(uint32_t a, uint32_t& r0, uint32_t& r1,
                                         uint32_t& r2, uint32_t& r3){
    asm volatile("ldmatrix.sync.aligned.m8n8.x4.trans.shared.b16 {%0,%1,%2,%3}, [%4];"
                 : "=r"(r0), "=r"(r1), "=r"(r2), "=r"(r3) : "r"(a));
}
__device__ __forceinline__ void mma_bf16(float* c, const uint32_t* a,
                                         uint32_t b0, uint32_t b1){
    asm volatile(
      "mma.sync.aligned.m16n8k16.row.col.f32.bf16.bf16.f32 "
      "{%0,%1,%2,%3}, {%4,%5,%6,%7}, {%8,%9}, {%0,%1,%2,%3};"
      : "+f"(c[0]), "+f"(c[1]), "+f"(c[2]), "+f"(c[3])
      : "r"(a[0]), "r"(a[1]), "r"(a[2]), "r"(a[3]), "r"(b0), "r"(b1));
}
__device__ __forceinline__ uint32_t pkbf(__nv_bfloat16 a, __nv_bfloat16 b){
    union { __nv_bfloat16 h[2]; uint32_t u; } t;
    t.h[0] = a; t.h[1] = b;
    return t.u;
}
__device__ __forceinline__ uint32_t hilo_hi2(float v0, float v1,
                                             uint32_t& lo_out){
    __nv_bfloat16 h0 = __float2bfloat16(v0), h1 = __float2bfloat16(v1);
    lo_out = pkbf(__float2bfloat16(v0 - __bfloat162float(h0)),
                  __float2bfloat16(v1 - __bfloat162float(h1)));
    return pkbf(h0, h1);
}

// ============================================================================
// bf16x3 tensor-core GEMM:  C = A @ B^T + bias.  Output either fp32 C, or
// bf16 hi/lo pair (Chi/Clo) when Chi != nullptr (fused split for next stage).
// CTA tile 128x128, 4 warps x 64x64, BK=32, cp.async double buffer. (At the
// legacy-HMMA rt=8 ceiling; do not touch.)
// ============================================================================
#define GBM 128
#define GBN 128
#define GBK 32
#define ROWP 40
#define TILE_B (128 * ROWP * 2)
#define STAGE_B (4 * TILE_B)
#define GM_SMEM (2 * STAGE_B)

__global__ __launch_bounds__(128, 2) void gemm_bf16x3(
    const __nv_bfloat16* __restrict__ Ahi, const __nv_bfloat16* __restrict__ Alo,
    const __nv_bfloat16* __restrict__ Bhi, const __nv_bfloat16* __restrict__ Blo,
    const float* __restrict__ bias, float* __restrict__ C,
    __nv_bfloat16* __restrict__ Chi, __nv_bfloat16* __restrict__ Clo,
    int M, int N, int K)
{
    extern __shared__ __align__(16) char smem[];
    const uint32_t sb = smem_u32(smem);

    const int tid  = threadIdx.x;
    const int w    = tid >> 5;
    const int lane = tid & 31;
    const int bm   = blockIdx.y * GBM;
    const int bn   = blockIdx.x * GBN;
    const int wm   = (w & 1) * 64;
    const int wn   = (w >> 1) * 64;

    const __nv_bfloat16* gA_hi = Ahi + (size_t)bm * K;
    const __nv_bfloat16* gA_lo = Alo + (size_t)bm * K;
    const __nv_bfloat16* gB_hi = Bhi + (size_t)bn * K;
    const __nv_bfloat16* gB_lo = Blo + (size_t)bn * K;

    auto load_stage = [&](int s, int k0){
        const uint32_t dstb = sb + s * STAGE_B;
        const __nv_bfloat16* srcs[4] = { gA_hi, gA_lo, gB_hi, gB_lo };
#pragma unroll
        for (int t = 0; t < 4; t++) {
            const __nv_bfloat16* g = srcs[t];
            const uint32_t db = dstb + t * TILE_B;
#pragma unroll
            for (int i = 0; i < 4; i++) {
                const int idx = i * 128 + tid;
                const int row = idx >> 2;
                const int kq  = idx & 3;
                cp16(db + row * 80 + kq * 16, g + (size_t)row * K + k0 + kq * 8);
            }
        }
        cp_commit();
    };

    float acc[4][8][4];
#pragma unroll
    for (int mt = 0; mt < 4; mt++)
#pragma unroll
        for (int nt = 0; nt < 8; nt++)
#pragma unroll
            for (int r = 0; r < 4; r++) acc[mt][nt][r] = 0.f;

    const int nchunks = K / GBK;
    load_stage(0, 0);

    const int a_row  = lane & 15;
    const int a_koff = (lane >> 4) << 3;
    const int b_row  = (lane & 7) + ((lane >> 4) << 3);
    const int b_koff = ((lane >> 3) & 1) << 3;

    for (int ic = 0; ic < nchunks; ic++) {
        if (ic + 1 < nchunks) load_stage((ic + 1) & 1, (ic + 1) * GBK);
        if (ic + 1 < nchunks) cp_wait<1>(); else cp_wait<0>();
        __syncthreads();

        const uint32_t st = sb + (ic & 1) * STAGE_B;
        const uint32_t sAhi = st;
        const uint32_t sAlo = st + TILE_B;
        const uint32_t sBhi = st + 2 * TILE_B;
        const uint32_t sBlo = st + 3 * TILE_B;

#pragma unroll
        for (int ks = 0; ks < 2; ks++) {
            const int kb = ks * 16;
            uint32_t ahi[4][4], alo[4][4];
#pragma unroll
            for (int mt = 0; mt < 4; mt++) {
                const uint32_t aoff =
                    (uint32_t)((wm + mt * 16 + a_row) * 80 + (kb + a_koff) * 2);
                ldm_x4(sAhi + aoff, ahi[mt][0], ahi[mt][1], ahi[mt][2], ahi[mt][3]);
                ldm_x4(sAlo + aoff, alo[mt][0], alo[mt][1], alo[mt][2], alo[mt][3]);
            }
#pragma unroll
            for (int np = 0; np < 4; np++) {
                const uint32_t boff =
                    (uint32_t)((wn + np * 16 + b_row) * 80 + (kb + b_koff) * 2);
                uint32_t bh0, bh1, bh2, bh3, bl0, bl1, bl2, bl3;
                ldm_x4(sBhi + boff, bh0, bh1, bh2, bh3);
                ldm_x4(sBlo + boff, bl0, bl1, bl2, bl3);
#pragma unroll
                for (int mt = 0; mt < 4; mt++) {
                    mma_bf16(acc[mt][2*np],   ahi[mt], bh0, bh1);
                    mma_bf16(acc[mt][2*np+1], ahi[mt], bh2, bh3);
                    mma_bf16(acc[mt][2*np],   ahi[mt], bl0, bl1);
                    mma_bf16(acc[mt][2*np+1], ahi[mt], bl2, bl3);
                    mma_bf16(acc[mt][2*np],   alo[mt], bh0, bh1);
                    mma_bf16(acc[mt][2*np+1], alo[mt], bh2, bh3);
                }
            }
        }
        __syncthreads();
    }

#pragma unroll
    for (int mt = 0; mt < 4; mt++) {
        const int r0 = bm + wm + mt * 16 + (lane >> 2);
#pragma unroll
        for (int nt = 0; nt < 8; nt++) {
            const int col = bn + wn + nt * 8 + ((lane & 3) << 1);
            const float2 bv = *(const float2*)&bias[col];
            float v0 = acc[mt][nt][0] + bv.x, v1 = acc[mt][nt][1] + bv.y;
            float v2 = acc[mt][nt][2] + bv.x, v3 = acc[mt][nt][3] + bv.y;
            if (Chi) {
                uint32_t lo0, lo1;
                uint32_t hi0 = hilo_hi2(v0, v1, lo0);
                uint32_t hi1 = hilo_hi2(v2, v3, lo1);
                *(uint32_t*)(Chi + (size_t)r0       * N + col) = hi0;
                *(uint32_t*)(Clo + (size_t)r0       * N + col) = lo0;
                *(uint32_t*)(Chi + (size_t)(r0 + 8) * N + col) = hi1;
                *(uint32_t*)(Clo + (size_t)(r0 + 8) * N + col) = lo1;
            } else {
                *(float2*)&C[(size_t)r0       * N + col] = make_float2(v0, v1);
                *(float2*)&C[(size_t)(r0 + 8) * N + col] = make_float2(v2, v3);
            }
        }
    }
}

// ============================================================================
// RoPE on q and k, operating in place on bf16 hi/lo arrays.
// ============================================================================
__global__ void rope_hilo_kernel(__nv_bfloat16* __restrict__ hi,
                                 __nv_bfloat16* __restrict__ lo)
{
    int idx = blockIdx.x * blockDim.x + threadIdx.x;      // SEQ*NH*16 total
    if (idx >= SEQ * NH * 16) return;
    const int d = idx & 15;
    const int h = (idx >> 4) & 31;
    const int t = idx >> 9;

    const float freq  = __expf(-(float)d * 0.5756462732485115f); // ln(1e4)/16
    const float theta = (float)t * freq;
    float s, c;
    sincosf(theta, &s, &c);

    size_t base = (size_t)t * QKV_N + h * HD + d;
#pragma unroll
    for (int qk = 0; qk < 2; qk++) {
        const size_t i1 = base + qk * DIMS;
        const size_t i2 = i1 + 16;
        float x1 = __bfloat162float(hi[i1]) + __bfloat162float(lo[i1]);
        float x2 = __bfloat162float(hi[i2]) + __bfloat162float(lo[i2]);
        float r1 = x1 * c - x2 * s;
        float r2 = x1 * s + x2 * c;
        __nv_bfloat16 h1 = __float2bfloat16(r1);
        __nv_bfloat16 h2 = __float2bfloat16(r2);
        hi[i1] = h1; lo[i1] = __float2bfloat16(r1 - __bfloat162float(h1));
        hi[i2] = h2; lo[i2] = __float2bfloat16(r2 - __bfloat162float(h2));
    }
}

// ============================================================================
// Tensor-core flash attention v2, causal, bf16x3.
// CTA = (head, 128 q-rows), 256 threads = 8 warps x 16 rows.
// K/V double-buffered (cp.async), next tile issued before compute,
// ONE __syncthreads per k-tile. 1 CTA/SM (132KB smem).
// ============================================================================
#define AP      88
#define SQH     0
#define SQL     (128*AP)                 // 11264
#define STG0    (2*128*AP)               // 22528
#define STG_SZ  (4*64*AP)                // 22528 (KH,KL,VH,VL)
#define KH_OFF  0
#define KL_OFF  (64*AP)
#define VH_OFF  (2*64*AP)
#define VL_OFF  (3*64*AP)
#define ATT_SMEM ((STG0 + 2*STG_SZ) * 2) // 135168 bytes

__global__ __launch_bounds__(256, 1) void attn_tc2(
    const __nv_bfloat16* __restrict__ qkvhi,
    const __nv_bfloat16* __restrict__ qkvlo,
    __nv_bfloat16* __restrict__ ohi,
    __nv_bfloat16* __restrict__ olo)
{
    extern __shared__ __align__(16) __nv_bfloat16 smA[];
    const uint32_t sb = smem_u32(smA);
    const int h  = blockIdx.x;
    const int qb = (gridDim.y - 1) - blockIdx.y;   // heavy tiles first
    const int tid = threadIdx.x, lane = tid & 31, w = tid >> 5;
    const int q0 = qb * 128;
    const float scale = 0.11180339887498949f;   // 1/sqrt(80)

    // ---- Q load (128 rows x 10 col-chunks, hi+lo) ----
    {
        const size_t off = (size_t)q0 * QKV_N + h * HD;
#pragma unroll
        for (int it = 0; it < 5; it++) {
            const int idx = it * 256 + tid;       // 1280 (row,col) pairs
            const int row = idx / 10, col = idx % 10;
            const size_t go = off + (size_t)row * QKV_N + col * 8;
            cp16(sb + (SQH + row * AP) * 2 + col * 16, qkvhi + go);
            cp16(sb + (SQL + row * AP) * 2 + col * 16, qkvlo + go);
        }
    }
    auto loadKV = [&](int kb, int s){
        const size_t koff = (size_t)(kb * 64) * QKV_N + DIMS + h * HD;
        const uint32_t stg = sb + (STG0 + s * STG_SZ) * 2;
#pragma unroll
        for (int it = 0; it < 3; it++) {
            const int idx = it * 256 + tid;       // 640 (row,col) pairs
            if (idx < 640) {
                const int row = idx / 10, col = idx % 10;
                const size_t gk = koff + (size_t)row * QKV_N + col * 8;
                const size_t gv = gk + DIMS;
                cp16(stg + (KH_OFF + row * AP) * 2 + col * 16, qkvhi + gk);
                cp16(stg + (KL_OFF + row * AP) * 2 + col * 16, qkvlo + gk);
                cp16(stg + (VH_OFF + row * AP) * 2 + col * 16, qkvhi + gv);
                cp16(stg + (VL_OFF + row * AP) * 2 + col * 16, qkvlo + gv);
            }
        }
    };

    float of[10][4];
#pragma unroll
    for (int i = 0; i < 10; i++)
#pragma unroll
        for (int j = 0; j < 4; j++) of[i][j] = 0.f;
    float mA = -1e30f, mB = -1e30f, lA = 0.f, lB = 0.f;

    loadKV(0, 0);
    cp_commit();

    const int a_row  = lane & 15;
    const int a_k    = (lane >> 4) << 3;
    const int b_row  = (lane & 7) + ((lane >> 4) << 3);
    const int b_k    = ((lane >> 3) & 1) << 3;
    const int vk     = (lane & 7) + (((lane >> 3) & 1) << 3);
    const int vd     = (lane >> 4) << 3;
    const int clb    = 2 * (lane & 3);
    const int rl     = w * 16 + (lane >> 2);   // local q row (A); B = +8

    const int ntiles = 2 * qb + 2;
    for (int kb = 0; kb < ntiles; kb++) {
        cp_wait<0>();
        __syncthreads();
        if (kb + 1 < ntiles) { loadKV(kb + 1, (kb + 1) & 1); cp_commit(); }

        const uint32_t stg = sb + (STG0 + (kb & 1) * STG_SZ) * 2;

        // ---- S = Q K^T (bf16x3) ----
        float sf[8][4];
#pragma unroll
        for (int i = 0; i < 8; i++)
#pragma unroll
            for (int j = 0; j < 4; j++) sf[i][j] = 0.f;

#pragma unroll
        for (int kc = 0; kc < 5; kc++) {
            uint32_t ahi[4], alo[4];
            const uint32_t aoff = (uint32_t)((w * 16 + a_row) * AP + kc * 16 + a_k) * 2;
            ldm_x4(sb + SQH * 2 + aoff, ahi[0], ahi[1], ahi[2], ahi[3]);
            ldm_x4(sb + SQL * 2 + aoff, alo[0], alo[1], alo[2], alo[3]);
#pragma unroll
            for (int bp = 0; bp < 4; bp++) {
                const uint32_t boff = (uint32_t)((bp * 16 + b_row) * AP + kc * 16 + b_k) * 2;
                uint32_t bh0, bh1, bh2, bh3, bl0, bl1, bl2, bl3;
                ldm_x4(stg + KH_OFF * 2 + boff, bh0, bh1, bh2, bh3);
                ldm_x4(stg + KL_OFF * 2 + boff, bl0, bl1, bl2, bl3);
                mma_bf16(sf[2*bp],   ahi, bh0, bh1);
                mma_bf16(sf[2*bp+1], ahi, bh2, bh3);
                mma_bf16(sf[2*bp],   ahi, bl0, bl1);
                mma_bf16(sf[2*bp+1], ahi, bl2, bl3);
                mma_bf16(sf[2*bp],   alo, bh0, bh1);
                mma_bf16(sf[2*bp+1], alo, bh2, bh3);
            }
        }

        // ---- scale + causal mask ----
        const bool needmask = (kb * 64 + 63 > q0 + w * 16);
#pragma unroll
        for (int nt = 0; nt < 8; nt++) {
            const int c0 = kb * 64 + nt * 8 + clb;
            const int grA = q0 + rl, grB = grA + 8;
#pragma unroll
            for (int j = 0; j < 2; j++) {
                float vA = sf[nt][j]     * scale;
                float vB = sf[nt][2 + j] * scale;
                if (needmask) {
                    if (c0 + j > grA) vA = -1e30f;
                    if (c0 + j > grB) vB = -1e30f;
                }
                sf[nt][j] = vA; sf[nt][2 + j] = vB;
            }
        }

        // ---- online softmax (register + quad shfl) ----
        float mxA = -1e30f, mxB = -1e30f;
#pragma unroll
        for (int nt = 0; nt < 8; nt++) {
            mxA = fmaxf(mxA, fmaxf(sf[nt][0], sf[nt][1]));
            mxB = fmaxf(mxB, fmaxf(sf[nt][2], sf[nt][3]));
        }
        mxA = fmaxf(mxA, __shfl_xor_sync(0xffffffffu, mxA, 1));
        mxA = fmaxf(mxA, __shfl_xor_sync(0xffffffffu, mxA, 2));
        mxB = fmaxf(mxB, __shfl_xor_sync(0xffffffffu, mxB, 1));
        mxB = fmaxf(mxB, __shfl_xor_sync(0xffffffffu, mxB, 2));
        const float mnA = fmaxf(mA, mxA), mnB = fmaxf(mB, mxB);
        const float alphaA = __expf(mA - mnA), alphaB = __expf(mB - mnB);
        mA = mnA; mB = mnB;

        float sA = 0.f, sB = 0.f;
#pragma unroll
        for (int nt = 0; nt < 8; nt++) {
#pragma unroll
            for (int j = 0; j < 2; j++) {
                float pA = __expf(sf[nt][j]     - mnA);
                float pB = __expf(sf[nt][2 + j] - mnB);
                sf[nt][j] = pA; sf[nt][2 + j] = pB;
                sA += pA; sB += pB;
            }
        }
        sA += __shfl_xor_sync(0xffffffffu, sA, 1);
        sA += __shfl_xor_sync(0xffffffffu, sA, 2);
        sB += __shfl_xor_sync(0xffffffffu, sB, 1);
        sB += __shfl_xor_sync(0xffffffffu, sB, 2);
        lA = lA * alphaA + sA;
        lB = lB * alphaB + sB;
#pragma unroll
        for (int d = 0; d < 10; d++) {
            of[d][0] *= alphaA; of[d][1] *= alphaA;
            of[d][2] *= alphaB; of[d][3] *= alphaB;
        }

        // ---- O += P V (bf16x3), P packed in registers ----
#pragma unroll
        for (int kc2 = 0; kc2 < 4; kc2++) {
            uint32_t aH[4], aL[4];
#pragma unroll
            for (int half = 0; half < 2; half++) {
                const int nt = 2 * kc2 + half;
                aH[half * 2 + 0] = hilo_hi2(sf[nt][0], sf[nt][1], aL[half * 2 + 0]);
                aH[half * 2 + 1] = hilo_hi2(sf[nt][2], sf[nt][3], aL[half * 2 + 1]);
            }
#pragma unroll
            for (int dp = 0; dp < 5; dp++) {
                const uint32_t voff = (uint32_t)((kc2 * 16 + vk) * AP + dp * 16 + vd) * 2;
                uint32_t vh0, vh1, vh2, vh3, vl0, vl1, vl2, vl3;
                ldm_x4_t(stg + VH_OFF * 2 + voff, vh0, vh1, vh2, vh3);
                ldm_x4_t(stg + VL_OFF * 2 + voff, vl0, vl1, vl2, vl3);
                mma_bf16(of[2*dp],   aH, vh0, vh1);
                mma_bf16(of[2*dp+1], aH, vh2, vh3);
                mma_bf16(of[2*dp],   aH, vl0, vl1);
                mma_bf16(of[2*dp+1], aH, vl2, vl3);
                mma_bf16(of[2*dp],   aL, vh0, vh1);
                mma_bf16(of[2*dp+1], aL, vh2, vh3);
            }
        }
    }

    // ---- epilogue: normalize, split hi/lo, store bf16 ----
    const float iA = 1.f / lA, iB = 1.f / lB;
    const int gA = q0 + w * 16 + (lane >> 2);
    const int colb = h * HD + clb;
#pragma unroll
    for (int nt = 0; nt < 10; nt++) {
        const int col = colb + nt * 8;
        uint32_t lo0, lo1;
        uint32_t hi0 = hilo_hi2(of[nt][0] * iA, of[nt][1] * iA, lo0);
        uint32_t hi1 = hilo_hi2(of[nt][2] * iB, of[nt][3] * iB, lo1);
        *(uint32_t*)(ohi + (size_t)gA * DIMS + col)       = hi0;
        *(uint32_t*)(olo + (size_t)gA * DIMS + col)       = lo0;
        *(uint32_t*)(ohi + (size_t)(gA + 8) * DIMS + col) = hi1;
        *(uint32_t*)(olo + (size_t)(gA + 8) * DIMS + col) = lo1;
    }
}

// ============================================================================
extern "C" void kernel_launch(void* const* d_in, const int* in_sizes, int n_in,
                              void* d_out, int out_size)
{
    const float* x       = (const float*)d_in[0];
    const float* Wqkv_w  = (const float*)d_in[1];
    const float* Wqkv_b  = (const float*)d_in[2];
    const float* out_w   = (const float*)d_in[3];
    const float* out_b   = (const float*)d_in[4];
    // d_in[5] = mask: causal triu(-1e9), implemented structurally; unused.
    float* outp = (float*)d_out;

    __nv_bfloat16 *xhi, *xlo, *w1hi, *w1lo, *w2hi, *w2lo, *ahi, *alo, *qvh, *qvl;
    cudaGetSymbolAddress((void**)&xhi,  g_xhi);   cudaGetSymbolAddress((void**)&xlo,  g_xlo);
    cudaGetSymbolAddress((void**)&w1hi, g_w1hi);  cudaGetSymbolAddress((void**)&w1lo, g_w1lo);
    cudaGetSymbolAddress((void**)&w2hi, g_w2hi);  cudaGetSymbolAddress((void**)&w2lo, g_w2lo);
    cudaGetSymbolAddress((void**)&ahi,  g_ahi);   cudaGetSymbolAddress((void**)&alo,  g_alo);
    cudaGetSymbolAddress((void**)&qvh,  g_qkvhi); cudaGetSymbolAddress((void**)&qvl,  g_qkvlo);

    cudaFuncSetAttribute(gemm_bf16x3,
                         cudaFuncAttributeMaxDynamicSharedMemorySize, GM_SMEM);
    cudaFuncSetAttribute(attn_tc2,
                         cudaFuncAttributeMaxDynamicSharedMemorySize, ATT_SMEM);

    // 0) split-precision conversions of x and weights
    {
        int n4 = (SEQ * DIMS) / 4;
        cvt_hilo_kernel<<<(n4 + 255) / 256, 256>>>(x, xhi, xlo, n4);
        n4 = (QKV_N * DIMS) / 4;
        cvt_hilo_kernel<<<(n4 + 255) / 256, 256>>>(Wqkv_w, w1hi, w1lo, n4);
        n4 = (DIMS * DIMS) / 4;
        cvt_hilo_kernel<<<(n4 + 255) / 256, 256>>>(out_w, w2hi, w2lo, n4);
    }
    // 1) QKV projection -> bf16 hi/lo qkv directly (fused split epilogue)
    {
        dim3 grid(QKV_N / GBN, SEQ / GBM);
        gemm_bf16x3<<<grid, 128, GM_SMEM>>>(xhi, xlo, w1hi, w1lo,
                                            Wqkv_b, nullptr, qvh, qvl,
                                            SEQ, QKV_N, DIMS);
    }
    // 2) RoPE on q,k (in place on hi/lo)
    {
        int total = SEQ * NH * 16;
        rope_hilo_kernel<<<(total + 255) / 256, 256>>>(qvh, qvl);
    }
    // 3) tensor-core causal flash attention v2 -> bf16 hi/lo attn out
    {
        dim3 grid(NH, SEQ / 128);
        attn_tc2<<<grid, 256, ATT_SMEM>>>(qvh, qvl, ahi, alo);
    }
    // 4) output projection -> fp32 final output
    {
        dim3 grid(DIMS / GBN, SEQ / GBM);
        gemm_bf16x3<<<grid, 128, GM_SMEM>>>(ahi, alo, w2hi, w2lo,
                                            out_b, outp, nullptr, nullptr,
                                            SEQ, DIMS, DIMS);
    }
}

// round 10
// speedup vs baseline: 2.6110x; 2.4800x over previous
#include <cuda_runtime.h>
#include <cuda_fp16.h>
#include <math.h>
#include <stdint.h>

#define DIMS   2560
#define NH     32
#define HD     80
#define SEQ    2048
#define QKV_N  (3*DIMS)

// ---------------- scratch (static device globals; no runtime allocation) ----
__device__ __half g_xh  [SEQ * DIMS];
__device__ __half g_w1h [QKV_N * DIMS];
__device__ __half g_w2h [DIMS * DIMS];
__device__ __half g_aoh [SEQ * DIMS];     // attention out (fp16)
__device__ __half g_qkvh[SEQ * QKV_N];    // qkv (fp16), rope applied in place

// ============================================================================
// fp32 -> fp16 conversion (vectorized, memory bound)
// ============================================================================
__global__ void cvt_f16_kernel(const float* __restrict__ src,
                               __half* __restrict__ dst, int n4)
{
    int i = blockIdx.x * blockDim.x + threadIdx.x;
    if (i >= n4) return;
    float4 v = ((const float4*)src)[i];
    union { __half h[4]; uint2 u; } H;
    H.h[0] = __float2half_rn(v.x); H.h[1] = __float2half_rn(v.y);
    H.h[2] = __float2half_rn(v.z); H.h[3] = __float2half_rn(v.w);
    ((uint2*)dst)[i] = H.u;
}

// ============================================================================
// PTX helpers (baseline compute_103-safe)
// ============================================================================
__device__ __forceinline__ uint32_t smem_u32(const void* p){
    uint32_t a;
    asm("{ .reg .u64 t; cvta.to.shared.u64 t, %1; cvt.u32.u64 %0, t; }"
        : "=r"(a) : "l"(p));
    return a;
}
__device__ __forceinline__ void cp16(uint32_t dst, const void* src){
    asm volatile("cp.async.ca.shared.global [%0], [%1], 16;"
                 :: "r"(dst), "l"(src) : "memory");
}
__device__ __forceinline__ void cp_commit(){
    asm volatile("cp.async.commit_group;" ::: "memory");
}
template<int N> __device__ __forceinline__ void cp_wait(){
    asm volatile("cp.async.wait_group %0;" :: "n"(N) : "memory");
}
__device__ __forceinline__ void ldm_x4(uint32_t a, uint32_t& r0, uint32_t& r1,
                                       uint32_t& r2, uint32_t& r3){
    asm volatile("ldmatrix.sync.aligned.m8n8.x4.shared.b16 {%0,%1,%2,%3}, [%4];"
                 : "=r"(r0), "=r"(r1), "=r"(r2), "=r"(r3) : "r"(a));
}
__device__ __forceinline__ void ldm_x4_t(uint32_t a, uint32_t& r0, uint32_t& r1,
                                         uint32_t& r2, uint32_t& r3){
    asm volatile("ldmatrix.sync.aligned.m8n8.x4.trans.shared.b16 {%0,%1,%2,%3}, [%4];"
                 : "=r"(r0), "=r"(r1), "=r"(r2), "=r"(r3) : "r"(a));
}
__device__ __forceinline__ void mma_f16(float* c, const uint32_t* a,
                                        uint32_t b0, uint32_t b1){
    asm volatile(
      "mma.sync.aligned.m16n8k16.row.col.f32.f16.f16.f32 "
      "{%0,%1,%2,%3}, {%4,%5,%6,%7}, {%8,%9}, {%0,%1,%2,%3};"
      : "+f"(c[0]), "+f"(c[1]), "+f"(c[2]), "+f"(c[3])
      : "r"(a[0]), "r"(a[1]), "r"(a[2]), "r"(a[3]), "r"(b0), "r"(b1));
}
__device__ __forceinline__ uint32_t pkh(float a, float b){
    __half2 t = __floats2half2_rn(a, b);
    return *(uint32_t*)&t;
}

// ============================================================================
// fp16 tensor-core GEMM:  C = A @ B^T + bias  (single-term, fp32 accumulate)
// CTA tile 128x128, 4 warps x 64x64, BK=32, cp.async double buffer.
// Output fp32 C, or fp16 Ch when Ch != nullptr.
// ============================================================================
#define GBM 128
#define GBN 128
#define GBK 32
#define TILE_B (128 * 80)        // 128 rows x 80B (64B payload + 16B pad)
#define STAGE_B (2 * TILE_B)     // A, B
#define GM_SMEM (2 * STAGE_B)    // 40960 bytes

__global__ __launch_bounds__(128, 2) void gemm_f16(
    const __half* __restrict__ A, const __half* __restrict__ B,
    const float* __restrict__ bias, float* __restrict__ C,
    __half* __restrict__ Ch,
    int M, int N, int K)
{
    extern __shared__ __align__(16) char smem[];
    const uint32_t sb = smem_u32(smem);

    const int tid  = threadIdx.x;
    const int w    = tid >> 5;
    const int lane = tid & 31;
    const int bm   = blockIdx.y * GBM;
    const int bn   = blockIdx.x * GBN;
    const int wm   = (w & 1) * 64;
    const int wn   = (w >> 1) * 64;

    const __half* gA = A + (size_t)bm * K;
    const __half* gB = B + (size_t)bn * K;

    auto load_stage = [&](int s, int k0){
        const uint32_t dstb = sb + s * STAGE_B;
        const __half* srcs[2] = { gA, gB };
#pragma unroll
        for (int t = 0; t < 2; t++) {
            const __half* g = srcs[t];
            const uint32_t db = dstb + t * TILE_B;
#pragma unroll
            for (int i = 0; i < 4; i++) {
                const int idx = i * 128 + tid;
                const int row = idx >> 2;
                const int kq  = idx & 3;
                cp16(db + row * 80 + kq * 16, g + (size_t)row * K + k0 + kq * 8);
            }
        }
        cp_commit();
    };

    float acc[4][8][4];
#pragma unroll
    for (int mt = 0; mt < 4; mt++)
#pragma unroll
        for (int nt = 0; nt < 8; nt++)
#pragma unroll
            for (int r = 0; r < 4; r++) acc[mt][nt][r] = 0.f;

    const int nchunks = K / GBK;
    load_stage(0, 0);

    const int a_row  = lane & 15;
    const int a_koff = (lane >> 4) << 3;
    const int b_row  = (lane & 7) + ((lane >> 4) << 3);
    const int b_koff = ((lane >> 3) & 1) << 3;

    for (int ic = 0; ic < nchunks; ic++) {
        if (ic + 1 < nchunks) load_stage((ic + 1) & 1, (ic + 1) * GBK);
        if (ic + 1 < nchunks) cp_wait<1>(); else cp_wait<0>();
        __syncthreads();

        const uint32_t st = sb + (ic & 1) * STAGE_B;
        const uint32_t sA = st;
        const uint32_t sB = st + TILE_B;

#pragma unroll
        for (int ks = 0; ks < 2; ks++) {
            const int kb = ks * 16;
            uint32_t af[4][4];
#pragma unroll
            for (int mt = 0; mt < 4; mt++) {
                const uint32_t aoff =
                    (uint32_t)((wm + mt * 16 + a_row) * 80 + (kb + a_koff) * 2);
                ldm_x4(sA + aoff, af[mt][0], af[mt][1], af[mt][2], af[mt][3]);
            }
#pragma unroll
            for (int np = 0; np < 4; np++) {
                const uint32_t boff =
                    (uint32_t)((wn + np * 16 + b_row) * 80 + (kb + b_koff) * 2);
                uint32_t b0, b1, b2, b3;
                ldm_x4(sB + boff, b0, b1, b2, b3);
#pragma unroll
                for (int mt = 0; mt < 4; mt++) {
                    mma_f16(acc[mt][2*np],   af[mt], b0, b1);
                    mma_f16(acc[mt][2*np+1], af[mt], b2, b3);
                }
            }
        }
        __syncthreads();
    }

#pragma unroll
    for (int mt = 0; mt < 4; mt++) {
        const int r0 = bm + wm + mt * 16 + (lane >> 2);
#pragma unroll
        for (int nt = 0; nt < 8; nt++) {
            const int col = bn + wn + nt * 8 + ((lane & 3) << 1);
            const float2 bv = *(const float2*)&bias[col];
            float v0 = acc[mt][nt][0] + bv.x, v1 = acc[mt][nt][1] + bv.y;
            float v2 = acc[mt][nt][2] + bv.x, v3 = acc[mt][nt][3] + bv.y;
            if (Ch) {
                *(uint32_t*)(Ch + (size_t)r0       * N + col) = pkh(v0, v1);
                *(uint32_t*)(Ch + (size_t)(r0 + 8) * N + col) = pkh(v2, v3);
            } else {
                *(float2*)&C[(size_t)r0       * N + col] = make_float2(v0, v1);
                *(float2*)&C[(size_t)(r0 + 8) * N + col] = make_float2(v2, v3);
            }
        }
    }
}

// ============================================================================
// RoPE on q and k, in place on fp16 qkv.
// ============================================================================
__global__ void rope_f16_kernel(__half* __restrict__ qkv)
{
    int idx = blockIdx.x * blockDim.x + threadIdx.x;      // SEQ*NH*16 total
    if (idx >= SEQ * NH * 16) return;
    const int d = idx & 15;
    const int h = (idx >> 4) & 31;
    const int t = idx >> 9;

    const float freq  = __expf(-(float)d * 0.5756462732485115f); // ln(1e4)/16
    const float theta = (float)t * freq;
    float s, c;
    sincosf(theta, &s, &c);

    size_t base = (size_t)t * QKV_N + h * HD + d;
#pragma unroll
    for (int qk = 0; qk < 2; qk++) {
        const size_t i1 = base + qk * DIMS;
        const size_t i2 = i1 + 16;
        float x1 = __half2float(qkv[i1]);
        float x2 = __half2float(qkv[i2]);
        qkv[i1] = __float2half_rn(x1 * c - x2 * s);
        qkv[i2] = __float2half_rn(x1 * s + x2 * c);
    }
}

// ============================================================================
// Tensor-core flash attention, causal, fp16 single-term.
// CTA = (head, 128 q-rows), 256 threads = 8 warps x 16 rows.
// K/V double-buffered cp.async, one __syncthreads per k-tile.
// ============================================================================
#define AP      88                       // halves per smem row (176B pitch)
#define SQH     0
#define STG0    (128*AP)                 // after Q tile
#define STG_SZ  (2*64*AP)                // KH + VH
#define KH_OFF  0
#define VH_OFF  (64*AP)
#define ATT_SMEM ((STG0 + 2*STG_SZ) * 2) // 67584 bytes

__global__ __launch_bounds__(256, 1) void attn_f16(
    const __half* __restrict__ qkvh,
    __half* __restrict__ aoh)
{
    extern __shared__ __align__(16) __half smA[];
    const uint32_t sb = smem_u32(smA);
    const int h  = blockIdx.x;
    const int qb = (gridDim.y - 1) - blockIdx.y;   // heavy tiles first
    const int tid = threadIdx.x, lane = tid & 31, w = tid >> 5;
    const int q0 = qb * 128;
    const float scale = 0.11180339887498949f;   // 1/sqrt(80)

    // ---- Q load (128 rows x 10 col-chunks) ----
    {
        const size_t off = (size_t)q0 * QKV_N + h * HD;
#pragma unroll
        for (int it = 0; it < 5; it++) {
            const int idx = it * 256 + tid;       // 1280 chunks
            const int row = idx / 10, col = idx % 10;
            cp16(sb + (SQH + row * AP) * 2 + col * 16,
                 qkvh + off + (size_t)row * QKV_N + col * 8);
        }
    }
    auto loadKV = [&](int kb, int s){
        const size_t koff = (size_t)(kb * 64) * QKV_N + DIMS + h * HD;
        const uint32_t stg = sb + (STG0 + s * STG_SZ) * 2;
#pragma unroll
        for (int it = 0; it < 3; it++) {
            const int idx = it * 256 + tid;       // 640 (row,col) pairs
            if (idx < 640) {
                const int row = idx / 10, col = idx % 10;
                const size_t gk = koff + (size_t)row * QKV_N + col * 8;
                cp16(stg + (KH_OFF + row * AP) * 2 + col * 16, qkvh + gk);
                cp16(stg + (VH_OFF + row * AP) * 2 + col * 16, qkvh + gk + DIMS);
            }
        }
    };

    float of[10][4];
#pragma unroll
    for (int i = 0; i < 10; i++)
#pragma unroll
        for (int j = 0; j < 4; j++) of[i][j] = 0.f;
    float mA = -1e30f, mB = -1e30f, lA = 0.f, lB = 0.f;

    loadKV(0, 0);
    cp_commit();

    const int a_row  = lane & 15;
    const int a_k    = (lane >> 4) << 3;
    const int b_row  = (lane & 7) + ((lane >> 4) << 3);
    const int b_k    = ((lane >> 3) & 1) << 3;
    const int vk     = (lane & 7) + (((lane >> 3) & 1) << 3);
    const int vd     = (lane >> 4) << 3;
    const int clb    = 2 * (lane & 3);
    const int rl     = w * 16 + (lane >> 2);   // local q row (A); B = +8

    const int ntiles = 2 * qb + 2;
    for (int kb = 0; kb < ntiles; kb++) {
        cp_wait<0>();
        __syncthreads();
        if (kb + 1 < ntiles) { loadKV(kb + 1, (kb + 1) & 1); cp_commit(); }

        const uint32_t stg = sb + (STG0 + (kb & 1) * STG_SZ) * 2;

        // ---- S = Q K^T ----
        float sf[8][4];
#pragma unroll
        for (int i = 0; i < 8; i++)
#pragma unroll
            for (int j = 0; j < 4; j++) sf[i][j] = 0.f;

#pragma unroll
        for (int kc = 0; kc < 5; kc++) {
            uint32_t aq[4];
            const uint32_t aoff = (uint32_t)((w * 16 + a_row) * AP + kc * 16 + a_k) * 2;
            ldm_x4(sb + SQH * 2 + aoff, aq[0], aq[1], aq[2], aq[3]);
#pragma unroll
            for (int bp = 0; bp < 4; bp++) {
                const uint32_t boff = (uint32_t)((bp * 16 + b_row) * AP + kc * 16 + b_k) * 2;
                uint32_t b0, b1, b2, b3;
                ldm_x4(stg + KH_OFF * 2 + boff, b0, b1, b2, b3);
                mma_f16(sf[2*bp],   aq, b0, b1);
                mma_f16(sf[2*bp+1], aq, b2, b3);
            }
        }

        // ---- scale + causal mask ----
        const bool needmask = (kb * 64 + 63 > q0 + w * 16);
#pragma unroll
        for (int nt = 0; nt < 8; nt++) {
            const int c0 = kb * 64 + nt * 8 + clb;
            const int grA = q0 + rl, grB = grA + 8;
#pragma unroll
            for (int j = 0; j < 2; j++) {
                float vA = sf[nt][j]     * scale;
                float vB = sf[nt][2 + j] * scale;
                if (needmask) {
                    if (c0 + j > grA) vA = -1e30f;
                    if (c0 + j > grB) vB = -1e30f;
                }
                sf[nt][j] = vA; sf[nt][2 + j] = vB;
            }
        }

        // ---- online softmax (register + quad shfl) ----
        float mxA = -1e30f, mxB = -1e30f;
#pragma unroll
        for (int nt = 0; nt < 8; nt++) {
            mxA = fmaxf(mxA, fmaxf(sf[nt][0], sf[nt][1]));
            mxB = fmaxf(mxB, fmaxf(sf[nt][2], sf[nt][3]));
        }
        mxA = fmaxf(mxA, __shfl_xor_sync(0xffffffffu, mxA, 1));
        mxA = fmaxf(mxA, __shfl_xor_sync(0xffffffffu, mxA, 2));
        mxB = fmaxf(mxB, __shfl_xor_sync(0xffffffffu, mxB, 1));
        mxB = fmaxf(mxB, __shfl_xor_sync(0xffffffffu, mxB, 2));
        const float mnA = fmaxf(mA, mxA), mnB = fmaxf(mB, mxB);
        const float alphaA = __expf(mA - mnA), alphaB = __expf(mB - mnB);
        mA = mnA; mB = mnB;

        float sA = 0.f, sB = 0.f;
#pragma unroll
        for (int nt = 0; nt < 8; nt++) {
#pragma unroll
            for (int j = 0; j < 2; j++) {
                float pA = __expf(sf[nt][j]     - mnA);
                float pB = __expf(sf[nt][2 + j] - mnB);
                sf[nt][j] = pA; sf[nt][2 + j] = pB;
                sA += pA; sB += pB;
            }
        }
        sA += __shfl_xor_sync(0xffffffffu, sA, 1);
        sA += __shfl_xor_sync(0xffffffffu, sA, 2);
        sB += __shfl_xor_sync(0xffffffffu, sB, 1);
        sB += __shfl_xor_sync(0xffffffffu, sB, 2);
        lA = lA * alphaA + sA;
        lB = lB * alphaB + sB;
#pragma unroll
        for (int d = 0; d < 10; d++) {
            of[d][0] *= alphaA; of[d][1] *= alphaA;
            of[d][2] *= alphaB; of[d][3] *= alphaB;
        }

        // ---- O += P V, P packed to fp16 in registers ----
#pragma unroll
        for (int kc2 = 0; kc2 < 4; kc2++) {
            uint32_t aP[4];
#pragma unroll
            for (int half = 0; half < 2; half++) {
                const int nt = 2 * kc2 + half;
                aP[half * 2 + 0] = pkh(sf[nt][0], sf[nt][1]);
                aP[half * 2 + 1] = pkh(sf[nt][2], sf[nt][3]);
            }
#pragma unroll
            for (int dp = 0; dp < 5; dp++) {
                const uint32_t voff = (uint32_t)((kc2 * 16 + vk) * AP + dp * 16 + vd) * 2;
                uint32_t v0, v1, v2, v3;
                ldm_x4_t(stg + VH_OFF * 2 + voff, v0, v1, v2, v3);
                mma_f16(of[2*dp],   aP, v0, v1);
                mma_f16(of[2*dp+1], aP, v2, v3);
            }
        }
    }

    // ---- epilogue: normalize, store fp16 ----
    const float iA = 1.f / lA, iB = 1.f / lB;
    const int gA = q0 + w * 16 + (lane >> 2);
    const int colb = h * HD + clb;
#pragma unroll
    for (int nt = 0; nt < 10; nt++) {
        const int col = colb + nt * 8;
        *(uint32_t*)(aoh + (size_t)gA * DIMS + col)       =
            pkh(of[nt][0] * iA, of[nt][1] * iA);
        *(uint32_t*)(aoh + (size_t)(gA + 8) * DIMS + col) =
            pkh(of[nt][2] * iB, of[nt][3] * iB);
    }
}

// ============================================================================
extern "C" void kernel_launch(void* const* d_in, const int* in_sizes, int n_in,
                              void* d_out, int out_size)
{
    const float* x       = (const float*)d_in[0];
    const float* Wqkv_w  = (const float*)d_in[1];
    const float* Wqkv_b  = (const float*)d_in[2];
    const float* out_w   = (const float*)d_in[3];
    const float* out_b   = (const float*)d_in[4];
    // d_in[5] = mask: causal triu(-1e9), implemented structurally; unused.
    float* outp = (float*)d_out;

    __half *xh, *w1h, *w2h, *aoh, *qkvh;
    cudaGetSymbolAddress((void**)&xh,   g_xh);
    cudaGetSymbolAddress((void**)&w1h,  g_w1h);
    cudaGetSymbolAddress((void**)&w2h,  g_w2h);
    cudaGetSymbolAddress((void**)&aoh,  g_aoh);
    cudaGetSymbolAddress((void**)&qkvh, g_qkvh);

    cudaFuncSetAttribute(gemm_f16,
                         cudaFuncAttributeMaxDynamicSharedMemorySize, GM_SMEM);
    cudaFuncSetAttribute(attn_f16,
                         cudaFuncAttributeMaxDynamicSharedMemorySize, ATT_SMEM);

    // 0) fp16 conversions of x and weights
    {
        int n4 = (SEQ * DIMS) / 4;
        cvt_f16_kernel<<<(n4 + 255) / 256, 256>>>(x, xh, n4);
        n4 = (QKV_N * DIMS) / 4;
        cvt_f16_kernel<<<(n4 + 255) / 256, 256>>>(Wqkv_w, w1h, n4);
        n4 = (DIMS * DIMS) / 4;
        cvt_f16_kernel<<<(n4 + 255) / 256, 256>>>(out_w, w2h, n4);
    }
    // 1) QKV projection -> fp16 qkv directly
    {
        dim3 grid(QKV_N / GBN, SEQ / GBM);
        gemm_f16<<<grid, 128, GM_SMEM>>>(xh, w1h, Wqkv_b, nullptr, qkvh,
                                         SEQ, QKV_N, DIMS);
    }
    // 2) RoPE on q,k (in place, fp16)
    {
        int total = SEQ * NH * 16;
        rope_f16_kernel<<<(total + 255) / 256, 256>>>(qkvh);
    }
    // 3) tensor-core causal flash attention -> fp16 attn out
    {
        dim3 grid(NH, SEQ / 128);
        attn_f16<<<grid, 256, ATT_SMEM>>>(qkvh, aoh);
    }
    // 4) output projection -> fp32 final output
    {
        dim3 grid(DIMS / GBN, SEQ / GBM);
        gemm_f16<<<grid, 128, GM_SMEM>>>(aoh, w2h, out_b, outp, nullptr,
                                         SEQ, DIMS, DIMS);
    }
}

// round 11
// speedup vs baseline: 2.7606x; 1.0573x over previous
#include <cuda_runtime.h>
#include <cuda_fp16.h>
#include <math.h>
#include <stdint.h>

#define DIMS   2560
#define NH     32
#define HD     80
#define SEQ    2048
#define QKV_N  (3*DIMS)

// ---------------- scratch (static device globals; no runtime allocation) ----
__device__ __half g_xh  [SEQ * DIMS];
__device__ __half g_w1h [QKV_N * DIMS];
__device__ __half g_w2h [DIMS * DIMS];
__device__ __half g_aoh [SEQ * DIMS];     // attention out (fp16)
__device__ __half g_qkvh[SEQ * QKV_N];    // qkv (fp16), rope applied in place

// ============================================================================
// fp32 -> fp16 conversion (vectorized, memory bound)
// ============================================================================
__global__ void cvt_f16_kernel(const float* __restrict__ src,
                               __half* __restrict__ dst, int n4)
{
    int i = blockIdx.x * blockDim.x + threadIdx.x;
    if (i >= n4) return;
    float4 v = ((const float4*)src)[i];
    union { __half h[4]; uint2 u; } H;
    H.h[0] = __float2half_rn(v.x); H.h[1] = __float2half_rn(v.y);
    H.h[2] = __float2half_rn(v.z); H.h[3] = __float2half_rn(v.w);
    ((uint2*)dst)[i] = H.u;
}

// ============================================================================
// PTX helpers (baseline compute_103-safe)
// ============================================================================
__device__ __forceinline__ uint32_t smem_u32(const void* p){
    uint32_t a;
    asm("{ .reg .u64 t; cvta.to.shared.u64 t, %1; cvt.u32.u64 %0, t; }"
        : "=r"(a) : "l"(p));
    return a;
}
__device__ __forceinline__ void cp16(uint32_t dst, const void* src){
    asm volatile("cp.async.ca.shared.global [%0], [%1], 16;"
                 :: "r"(dst), "l"(src) : "memory");
}
__device__ __forceinline__ void cp_commit(){
    asm volatile("cp.async.commit_group;" ::: "memory");
}
template<int N> __device__ __forceinline__ void cp_wait(){
    asm volatile("cp.async.wait_group %0;" :: "n"(N) : "memory");
}
__device__ __forceinline__ void ldm_x4(uint32_t a, uint32_t& r0, uint32_t& r1,
                                       uint32_t& r2, uint32_t& r3){
    asm volatile("ldmatrix.sync.aligned.m8n8.x4.shared.b16 {%0,%1,%2,%3}, [%4];"
                 : "=r"(r0), "=r"(r1), "=r"(r2), "=r"(r3) : "r"(a));
}
__device__ __forceinline__ void ldm_x4_t(uint32_t a, uint32_t& r0, uint32_t& r1,
                                         uint32_t& r2, uint32_t& r3){
    asm volatile("ldmatrix.sync.aligned.m8n8.x4.trans.shared.b16 {%0,%1,%2,%3}, [%4];"
                 : "=r"(r0), "=r"(r1), "=r"(r2), "=r"(r3) : "r"(a));
}
__device__ __forceinline__ void mma_f16(float* c, const uint32_t* a,
                                        uint32_t b0, uint32_t b1){
    asm volatile(
      "mma.sync.aligned.m16n8k16.row.col.f32.f16.f16.f32 "
      "{%0,%1,%2,%3}, {%4,%5,%6,%7}, {%8,%9}, {%0,%1,%2,%3};"
      : "+f"(c[0]), "+f"(c[1]), "+f"(c[2]), "+f"(c[3])
      : "r"(a[0]), "r"(a[1]), "r"(a[2]), "r"(a[3]), "r"(b0), "r"(b1));
}
__device__ __forceinline__ uint32_t pkh(float a, float b){
    __half2 t = __floats2half2_rn(a, b);
    return *(uint32_t*)&t;
}

// ============================================================================
// fp16 tensor-core GEMM:  C = A @ B^T + bias  (single-term, fp32 accumulate)
// CTA 128x128, 4 warps x 64x64, BK=32, 3-stage cp.async pipeline,
// ONE __syncthreads per chunk. Output fp32 C, or fp16 Ch when Ch != nullptr.
// ============================================================================
#define GBM 128
#define GBN 128
#define GBK 32
#define TILE_B (128 * 80)        // 128 rows x 80B (64B payload + 16B pad)
#define STAGE_B (2 * TILE_B)     // A, B
#define GM_SMEM (3 * STAGE_B)    // 61440 bytes, 3 stages

__global__ __launch_bounds__(128, 2) void gemm_f16(
    const __half* __restrict__ A, const __half* __restrict__ B,
    const float* __restrict__ bias, float* __restrict__ C,
    __half* __restrict__ Ch,
    int M, int N, int K)
{
    extern __shared__ __align__(16) char smem[];
    const uint32_t sb = smem_u32(smem);

    const int tid  = threadIdx.x;
    const int w    = tid >> 5;
    const int lane = tid & 31;
    const int bm   = blockIdx.y * GBM;
    const int bn   = blockIdx.x * GBN;
    const int wm   = (w & 1) * 64;
    const int wn   = (w >> 1) * 64;

    const __half* gA = A + (size_t)bm * K;
    const __half* gB = B + (size_t)bn * K;

    auto load_stage = [&](int s, int k0){
        const uint32_t dstb = sb + s * STAGE_B;
        const __half* srcs[2] = { gA, gB };
#pragma unroll
        for (int t = 0; t < 2; t++) {
            const __half* g = srcs[t];
            const uint32_t db = dstb + t * TILE_B;
#pragma unroll
            for (int i = 0; i < 4; i++) {
                const int idx = i * 128 + tid;
                const int row = idx >> 2;
                const int kq  = idx & 3;
                cp16(db + row * 80 + kq * 16, g + (size_t)row * K + k0 + kq * 8);
            }
        }
        cp_commit();
    };

    float acc[4][8][4];
#pragma unroll
    for (int mt = 0; mt < 4; mt++)
#pragma unroll
        for (int nt = 0; nt < 8; nt++)
#pragma unroll
            for (int r = 0; r < 4; r++) acc[mt][nt][r] = 0.f;

    const int nchunks = K / GBK;
    load_stage(0, 0);
    load_stage(1, GBK);

    const int a_row  = lane & 15;
    const int a_koff = (lane >> 4) << 3;
    const int b_row  = (lane & 7) + ((lane >> 4) << 3);
    const int b_koff = ((lane >> 3) & 1) << 3;

    int stage = 0;
    for (int ic = 0; ic < nchunks; ic++) {
        cp_wait<1>();
        __syncthreads();
        // keep commit-group count invariant: empty group when past the end
        if (ic + 2 < nchunks) {
            int s2 = stage + 2; if (s2 >= 3) s2 -= 3;
            load_stage(s2, (ic + 2) * GBK);
        } else {
            cp_commit();
        }

        const uint32_t st = sb + stage * STAGE_B;
        const uint32_t sA = st;
        const uint32_t sB = st + TILE_B;

#pragma unroll
        for (int ks = 0; ks < 2; ks++) {
            const int kb = ks * 16;
            uint32_t af[4][4];
#pragma unroll
            for (int mt = 0; mt < 4; mt++) {
                const uint32_t aoff =
                    (uint32_t)((wm + mt * 16 + a_row) * 80 + (kb + a_koff) * 2);
                ldm_x4(sA + aoff, af[mt][0], af[mt][1], af[mt][2], af[mt][3]);
            }
#pragma unroll
            for (int np = 0; np < 4; np++) {
                const uint32_t boff =
                    (uint32_t)((wn + np * 16 + b_row) * 80 + (kb + b_koff) * 2);
                uint32_t b0, b1, b2, b3;
                ldm_x4(sB + boff, b0, b1, b2, b3);
#pragma unroll
                for (int mt = 0; mt < 4; mt++) {
                    mma_f16(acc[mt][2*np],   af[mt], b0, b1);
                    mma_f16(acc[mt][2*np+1], af[mt], b2, b3);
                }
            }
        }
        stage++; if (stage >= 3) stage -= 3;
    }

#pragma unroll
    for (int mt = 0; mt < 4; mt++) {
        const int r0 = bm + wm + mt * 16 + (lane >> 2);
#pragma unroll
        for (int nt = 0; nt < 8; nt++) {
            const int col = bn + wn + nt * 8 + ((lane & 3) << 1);
            const float2 bv = *(const float2*)&bias[col];
            float v0 = acc[mt][nt][0] + bv.x, v1 = acc[mt][nt][1] + bv.y;
            float v2 = acc[mt][nt][2] + bv.x, v3 = acc[mt][nt][3] + bv.y;
            if (Ch) {
                *(uint32_t*)(Ch + (size_t)r0       * N + col) = pkh(v0, v1);
                *(uint32_t*)(Ch + (size_t)(r0 + 8) * N + col) = pkh(v2, v3);
            } else {
                *(float2*)&C[(size_t)r0       * N + col] = make_float2(v0, v1);
                *(float2*)&C[(size_t)(r0 + 8) * N + col] = make_float2(v2, v3);
            }
        }
    }
}

// ============================================================================
// RoPE on q and k, in place on fp16 qkv.
// ============================================================================
__global__ void rope_f16_kernel(__half* __restrict__ qkv)
{
    int idx = blockIdx.x * blockDim.x + threadIdx.x;      // SEQ*NH*16 total
    if (idx >= SEQ * NH * 16) return;
    const int d = idx & 15;
    const int h = (idx >> 4) & 31;
    const int t = idx >> 9;

    const float freq  = __expf(-(float)d * 0.5756462732485115f); // ln(1e4)/16
    const float theta = (float)t * freq;
    float s, c;
    sincosf(theta, &s, &c);

    size_t base = (size_t)t * QKV_N + h * HD + d;
#pragma unroll
    for (int qk = 0; qk < 2; qk++) {
        const size_t i1 = base + qk * DIMS;
        const size_t i2 = i1 + 16;
        float x1 = __half2float(qkv[i1]);
        float x2 = __half2float(qkv[i2]);
        qkv[i1] = __float2half_rn(x1 * c - x2 * s);
        qkv[i2] = __float2half_rn(x1 * s + x2 * c);
    }
}

// ============================================================================
// Tensor-core flash attention, causal, fp16 single-term, occupancy 2.
// CTA = (head, 128 q-rows), 256 threads = 8 warps x 16 rows.
// Softmax: raw-score max tracking, exp2f with folded scale*log2e constant.
// ============================================================================
#define AP      88                       // halves per smem row (176B pitch)
#define SQH     0
#define STG0    (128*AP)                 // after Q tile
#define STG_SZ  (2*64*AP)                // KH + VH
#define KH_OFF  0
#define VH_OFF  (64*AP)
#define ATT_SMEM ((STG0 + 2*STG_SZ) * 2) // 67584 bytes

// scale * log2(e): exp(scale*(s-m)) == exp2(C2*(s-m))
#define C2EXP (0.11180339887498949f * 1.4426950408889634f)

__global__ __launch_bounds__(256, 2) void attn_f16(
    const __half* __restrict__ qkvh,
    __half* __restrict__ aoh)
{
    extern __shared__ __align__(16) __half smA[];
    const uint32_t sb = smem_u32(smA);
    const int h  = blockIdx.x;
    const int qb = (gridDim.y - 1) - blockIdx.y;   // heavy tiles first
    const int tid = threadIdx.x, lane = tid & 31, w = tid >> 5;
    const int q0 = qb * 128;

    // ---- Q load (128 rows x 10 col-chunks) ----
    {
        const size_t off = (size_t)q0 * QKV_N + h * HD;
#pragma unroll
        for (int it = 0; it < 5; it++) {
            const int idx = it * 256 + tid;       // 1280 chunks
            const int row = idx / 10, col = idx % 10;
            cp16(sb + (SQH + row * AP) * 2 + col * 16,
                 qkvh + off + (size_t)row * QKV_N + col * 8);
        }
    }
    auto loadKV = [&](int kb, int s){
        const size_t koff = (size_t)(kb * 64) * QKV_N + DIMS + h * HD;
        const uint32_t stg = sb + (STG0 + s * STG_SZ) * 2;
#pragma unroll
        for (int it = 0; it < 3; it++) {
            const int idx = it * 256 + tid;       // 640 (row,col) pairs
            if (idx < 640) {
                const int row = idx / 10, col = idx % 10;
                const size_t gk = koff + (size_t)row * QKV_N + col * 8;
                cp16(stg + (KH_OFF + row * AP) * 2 + col * 16, qkvh + gk);
                cp16(stg + (VH_OFF + row * AP) * 2 + col * 16, qkvh + gk + DIMS);
            }
        }
    };

    float of[10][4];
#pragma unroll
    for (int i = 0; i < 10; i++)
#pragma unroll
        for (int j = 0; j < 4; j++) of[i][j] = 0.f;
    float mA = -1e30f, mB = -1e30f, lA = 0.f, lB = 0.f;   // raw-unit maxima

    loadKV(0, 0);
    cp_commit();

    const int a_row  = lane & 15;
    const int a_k    = (lane >> 4) << 3;
    const int b_row  = (lane & 7) + ((lane >> 4) << 3);
    const int b_k    = ((lane >> 3) & 1) << 3;
    const int vk     = (lane & 7) + (((lane >> 3) & 1) << 3);
    const int vd     = (lane >> 4) << 3;
    const int clb    = 2 * (lane & 3);
    const int rl     = w * 16 + (lane >> 2);   // local q row (A); B = +8

    const int ntiles = 2 * qb + 2;
    for (int kb = 0; kb < ntiles; kb++) {
        cp_wait<0>();
        __syncthreads();
        if (kb + 1 < ntiles) { loadKV(kb + 1, (kb + 1) & 1); cp_commit(); }

        const uint32_t stg = sb + (STG0 + (kb & 1) * STG_SZ) * 2;

        // ---- S = Q K^T (raw units) ----
        float sf[8][4];
#pragma unroll
        for (int i = 0; i < 8; i++)
#pragma unroll
            for (int j = 0; j < 4; j++) sf[i][j] = 0.f;

#pragma unroll
        for (int kc = 0; kc < 5; kc++) {
            uint32_t aq[4];
            const uint32_t aoff = (uint32_t)((w * 16 + a_row) * AP + kc * 16 + a_k) * 2;
            ldm_x4(sb + SQH * 2 + aoff, aq[0], aq[1], aq[2], aq[3]);
#pragma unroll
            for (int bp = 0; bp < 4; bp++) {
                const uint32_t boff = (uint32_t)((bp * 16 + b_row) * AP + kc * 16 + b_k) * 2;
                uint32_t b0, b1, b2, b3;
                ldm_x4(stg + KH_OFF * 2 + boff, b0, b1, b2, b3);
                mma_f16(sf[2*bp],   aq, b0, b1);
                mma_f16(sf[2*bp+1], aq, b2, b3);
            }
        }

        // ---- causal mask (raw units) ----
        const bool needmask = (kb * 64 + 63 > q0 + w * 16);
        if (needmask) {
#pragma unroll
            for (int nt = 0; nt < 8; nt++) {
                const int c0 = kb * 64 + nt * 8 + clb;
                const int grA = q0 + rl, grB = grA + 8;
#pragma unroll
                for (int j = 0; j < 2; j++) {
                    if (c0 + j > grA) sf[nt][j]     = -1e30f;
                    if (c0 + j > grB) sf[nt][2 + j] = -1e30f;
                }
            }
        }

        // ---- online softmax: raw max + exp2 with folded constant ----
        float mxA = -1e30f, mxB = -1e30f;
#pragma unroll
        for (int nt = 0; nt < 8; nt++) {
            mxA = fmaxf(mxA, fmaxf(sf[nt][0], sf[nt][1]));
            mxB = fmaxf(mxB, fmaxf(sf[nt][2], sf[nt][3]));
        }
        mxA = fmaxf(mxA, __shfl_xor_sync(0xffffffffu, mxA, 1));
        mxA = fmaxf(mxA, __shfl_xor_sync(0xffffffffu, mxA, 2));
        mxB = fmaxf(mxB, __shfl_xor_sync(0xffffffffu, mxB, 1));
        mxB = fmaxf(mxB, __shfl_xor_sync(0xffffffffu, mxB, 2));
        const float mnA = fmaxf(mA, mxA), mnB = fmaxf(mB, mxB);
        const float alphaA = exp2f((mA - mnA) * C2EXP);
        const float alphaB = exp2f((mB - mnB) * C2EXP);
        mA = mnA; mB = mnB;
        const float cA = -mnA * C2EXP, cB = -mnB * C2EXP;

        float sA = 0.f, sB = 0.f;
#pragma unroll
        for (int nt = 0; nt < 8; nt++) {
#pragma unroll
            for (int j = 0; j < 2; j++) {
                float pA = exp2f(fmaf(sf[nt][j],     C2EXP, cA));
                float pB = exp2f(fmaf(sf[nt][2 + j], C2EXP, cB));
                sf[nt][j] = pA; sf[nt][2 + j] = pB;
                sA += pA; sB += pB;
            }
        }
        sA += __shfl_xor_sync(0xffffffffu, sA, 1);
        sA += __shfl_xor_sync(0xffffffffu, sA, 2);
        sB += __shfl_xor_sync(0xffffffffu, sB, 1);
        sB += __shfl_xor_sync(0xffffffffu, sB, 2);
        lA = lA * alphaA + sA;
        lB = lB * alphaB + sB;
#pragma unroll
        for (int d = 0; d < 10; d++) {
            of[d][0] *= alphaA; of[d][1] *= alphaA;
            of[d][2] *= alphaB; of[d][3] *= alphaB;
        }

        // ---- O += P V, P packed to fp16 in registers ----
#pragma unroll
        for (int kc2 = 0; kc2 < 4; kc2++) {
            uint32_t aP[4];
#pragma unroll
            for (int half = 0; half < 2; half++) {
                const int nt = 2 * kc2 + half;
                aP[half * 2 + 0] = pkh(sf[nt][0], sf[nt][1]);
                aP[half * 2 + 1] = pkh(sf[nt][2], sf[nt][3]);
            }
#pragma unroll
            for (int dp = 0; dp < 5; dp++) {
                const uint32_t voff = (uint32_t)((kc2 * 16 + vk) * AP + dp * 16 + vd) * 2;
                uint32_t v0, v1, v2, v3;
                ldm_x4_t(stg + VH_OFF * 2 + voff, v0, v1, v2, v3);
                mma_f16(of[2*dp],   aP, v0, v1);
                mma_f16(of[2*dp+1], aP, v2, v3);
            }
        }
    }

    // ---- epilogue: normalize, store fp16 ----
    const float iA = 1.f / lA, iB = 1.f / lB;
    const int gA = q0 + w * 16 + (lane >> 2);
    const int colb = h * HD + clb;
#pragma unroll
    for (int nt = 0; nt < 10; nt++) {
        const int col = colb + nt * 8;
        *(uint32_t*)(aoh + (size_t)gA * DIMS + col)       =
            pkh(of[nt][0] * iA, of[nt][1] * iA);
        *(uint32_t*)(aoh + (size_t)(gA + 8) * DIMS + col) =
            pkh(of[nt][2] * iB, of[nt][3] * iB);
    }
}

// ============================================================================
extern "C" void kernel_launch(void* const* d_in, const int* in_sizes, int n_in,
                              void* d_out, int out_size)
{
    const float* x       = (const float*)d_in[0];
    const float* Wqkv_w  = (const float*)d_in[1];
    const float* Wqkv_b  = (const float*)d_in[2];
    const float* out_w   = (const float*)d_in[3];
    const float* out_b   = (const float*)d_in[4];
    // d_in[5] = mask: causal triu(-1e9), implemented structurally; unused.
    float* outp = (float*)d_out;

    __half *xh, *w1h, *w2h, *aoh, *qkvh;
    cudaGetSymbolAddress((void**)&xh,   g_xh);
    cudaGetSymbolAddress((void**)&w1h,  g_w1h);
    cudaGetSymbolAddress((void**)&w2h,  g_w2h);
    cudaGetSymbolAddress((void**)&aoh,  g_aoh);
    cudaGetSymbolAddress((void**)&qkvh, g_qkvh);

    cudaFuncSetAttribute(gemm_f16,
                         cudaFuncAttributeMaxDynamicSharedMemorySize, GM_SMEM);
    cudaFuncSetAttribute(attn_f16,
                         cudaFuncAttributeMaxDynamicSharedMemorySize, ATT_SMEM);

    // 0) fp16 conversions of x and weights
    {
        int n4 = (SEQ * DIMS) / 4;
        cvt_f16_kernel<<<(n4 + 255) / 256, 256>>>(x, xh, n4);
        n4 = (QKV_N * DIMS) / 4;
        cvt_f16_kernel<<<(n4 + 255) / 256, 256>>>(Wqkv_w, w1h, n4);
        n4 = (DIMS * DIMS) / 4;
        cvt_f16_kernel<<<(n4 + 255) / 256, 256>>>(out_w, w2h, n4);
    }
    // 1) QKV projection -> fp16 qkv directly
    {
        dim3 grid(QKV_N / GBN, SEQ / GBM);
        gemm_f16<<<grid, 128, GM_SMEM>>>(xh, w1h, Wqkv_b, nullptr, qkvh,
                                         SEQ, QKV_N, DIMS);
    }
    // 2) RoPE on q,k (in place, fp16)
    {
        int total = SEQ * NH * 16;
        rope_f16_kernel<<<(total + 255) / 256, 256>>>(qkvh);
    }
    // 3) tensor-core causal flash attention -> fp16 attn out
    {
        dim3 grid(NH, SEQ / 128);
        attn_f16<<<grid, 256, ATT_SMEM>>>(qkvh, aoh);
    }
    // 4) output projection -> fp32 final output
    {
        dim3 grid(DIMS / GBN, SEQ / GBM);
        gemm_f16<<<grid, 128, GM_SMEM>>>(aoh, w2h, out_b, outp, nullptr,
                                         SEQ, DIMS, DIMS);
    }
}

// round 12
// speedup vs baseline: 2.7857x; 1.0091x over previous
#include <cuda_runtime.h>
#include <cuda_fp16.h>
#include <math.h>
#include <stdint.h>

#define DIMS   2560
#define NH     32
#define HD     80
#define SEQ    2048
#define QKV_N  (3*DIMS)

// ---------------- scratch (static device globals; no runtime allocation) ----
__device__ __half g_xh  [SEQ * DIMS];
__device__ __half g_w1h [QKV_N * DIMS];
__device__ __half g_w2h [DIMS * DIMS];
__device__ __half g_aoh [SEQ * DIMS];     // attention out (fp16)
__device__ __half g_qkvh[SEQ * QKV_N];    // qkv (fp16), rope applied in place

// ============================================================================
// fp32 -> fp16 conversion (vectorized, memory bound)
// ============================================================================
__global__ void cvt_f16_kernel(const float* __restrict__ src,
                               __half* __restrict__ dst, int n4)
{
    int i = blockIdx.x * blockDim.x + threadIdx.x;
    if (i >= n4) return;
    float4 v = ((const float4*)src)[i];
    union { __half h[4]; uint2 u; } H;
    H.h[0] = __float2half_rn(v.x); H.h[1] = __float2half_rn(v.y);
    H.h[2] = __float2half_rn(v.z); H.h[3] = __float2half_rn(v.w);
    ((uint2*)dst)[i] = H.u;
}

// ============================================================================
// PTX helpers (baseline compute_103-safe)
// ============================================================================
__device__ __forceinline__ uint32_t smem_u32(const void* p){
    uint32_t a;
    asm("{ .reg .u64 t; cvta.to.shared.u64 t, %1; cvt.u32.u64 %0, t; }"
        : "=r"(a) : "l"(p));
    return a;
}
__device__ __forceinline__ void cp16(uint32_t dst, const void* src){
    asm volatile("cp.async.ca.shared.global [%0], [%1], 16;"
                 :: "r"(dst), "l"(src) : "memory");
}
__device__ __forceinline__ void cp_commit(){
    asm volatile("cp.async.commit_group;" ::: "memory");
}
template<int N> __device__ __forceinline__ void cp_wait(){
    asm volatile("cp.async.wait_group %0;" :: "n"(N) : "memory");
}
__device__ __forceinline__ void ldm_x4(uint32_t a, uint32_t& r0, uint32_t& r1,
                                       uint32_t& r2, uint32_t& r3){
    asm volatile("ldmatrix.sync.aligned.m8n8.x4.shared.b16 {%0,%1,%2,%3}, [%4];"
                 : "=r"(r0), "=r"(r1), "=r"(r2), "=r"(r3) : "r"(a));
}
__device__ __forceinline__ void ldm_x4_t(uint32_t a, uint32_t& r0, uint32_t& r1,
                                         uint32_t& r2, uint32_t& r3){
    asm volatile("ldmatrix.sync.aligned.m8n8.x4.trans.shared.b16 {%0,%1,%2,%3}, [%4];"
                 : "=r"(r0), "=r"(r1), "=r"(r2), "=r"(r3) : "r"(a));
}
__device__ __forceinline__ void mma_f16(float* c, const uint32_t* a,
                                        uint32_t b0, uint32_t b1){
    asm volatile(
      "mma.sync.aligned.m16n8k16.row.col.f32.f16.f16.f32 "
      "{%0,%1,%2,%3}, {%4,%5,%6,%7}, {%8,%9}, {%0,%1,%2,%3};"
      : "+f"(c[0]), "+f"(c[1]), "+f"(c[2]), "+f"(c[3])
      : "r"(a[0]), "r"(a[1]), "r"(a[2]), "r"(a[3]), "r"(b0), "r"(b1));
}
__device__ __forceinline__ uint32_t pkh(float a, float b){
    __half2 t = __floats2half2_rn(a, b);
    return *(uint32_t*)&t;
}

// ============================================================================
// fp16 tensor-core GEMM, PERSISTENT version: grid = 296 CTAs, each loops
// over 128x128 tiles (t += gridDim.x) to remove wave-quantization tail.
// 3-stage cp.async pipeline, one __syncthreads per chunk.
// ============================================================================
#define GBK 32
#define TILE_B (128 * 80)        // 128 rows x 80B (64B payload + 16B pad)
#define STAGE_B (2 * TILE_B)     // A, B
#define GM_SMEM (3 * STAGE_B)    // 61440 bytes, 3 stages
#define GEMM_CTAS 296

__global__ __launch_bounds__(128, 2) void gemm_f16(
    const __half* __restrict__ A, const __half* __restrict__ B,
    const float* __restrict__ bias, float* __restrict__ C,
    __half* __restrict__ Ch,
    int M, int N, int K)
{
    extern __shared__ __align__(16) char smem[];
    const uint32_t sb = smem_u32(smem);

    const int tid  = threadIdx.x;
    const int w    = tid >> 5;
    const int lane = tid & 31;
    const int wm   = (w & 1) * 64;
    const int wn   = (w >> 1) * 64;

    const int tiles_n = N >> 7;
    const int total_tiles = (M >> 7) * tiles_n;

    const int a_row  = lane & 15;
    const int a_koff = (lane >> 4) << 3;
    const int b_row  = (lane & 7) + ((lane >> 4) << 3);
    const int b_koff = ((lane >> 3) & 1) << 3;
    const int nchunks = K / GBK;

    for (int t = blockIdx.x; t < total_tiles; t += gridDim.x) {
        const int bm = (t / tiles_n) << 7;
        const int bn = (t % tiles_n) << 7;
        const __half* gA = A + (size_t)bm * K;
        const __half* gB = B + (size_t)bn * K;

        auto load_stage = [&](int s, int k0){
            const uint32_t dstb = sb + s * STAGE_B;
            const __half* srcs[2] = { gA, gB };
#pragma unroll
            for (int u = 0; u < 2; u++) {
                const __half* g = srcs[u];
                const uint32_t db = dstb + u * TILE_B;
#pragma unroll
                for (int i = 0; i < 4; i++) {
                    const int idx = i * 128 + tid;
                    const int row = idx >> 2;
                    const int kq  = idx & 3;
                    cp16(db + row * 80 + kq * 16, g + (size_t)row * K + k0 + kq * 8);
                }
            }
            cp_commit();
        };

        float acc[4][8][4];
#pragma unroll
        for (int mt = 0; mt < 4; mt++)
#pragma unroll
            for (int nt = 0; nt < 8; nt++)
#pragma unroll
                for (int r = 0; r < 4; r++) acc[mt][nt][r] = 0.f;

        __syncthreads();            // protect smem reuse across tiles
        load_stage(0, 0);
        load_stage(1, GBK);

        int stage = 0;
        for (int ic = 0; ic < nchunks; ic++) {
            cp_wait<1>();
            __syncthreads();
            if (ic + 2 < nchunks) {
                int s2 = stage + 2; if (s2 >= 3) s2 -= 3;
                load_stage(s2, (ic + 2) * GBK);
            } else {
                cp_commit();        // keep group-count invariant
            }

            const uint32_t st = sb + stage * STAGE_B;
            const uint32_t sA = st;
            const uint32_t sB = st + TILE_B;

#pragma unroll
            for (int ks = 0; ks < 2; ks++) {
                const int kb = ks * 16;
                uint32_t af[4][4];
#pragma unroll
                for (int mt = 0; mt < 4; mt++) {
                    const uint32_t aoff =
                        (uint32_t)((wm + mt * 16 + a_row) * 80 + (kb + a_koff) * 2);
                    ldm_x4(sA + aoff, af[mt][0], af[mt][1], af[mt][2], af[mt][3]);
                }
#pragma unroll
                for (int np = 0; np < 4; np++) {
                    const uint32_t boff =
                        (uint32_t)((wn + np * 16 + b_row) * 80 + (kb + b_koff) * 2);
                    uint32_t b0, b1, b2, b3;
                    ldm_x4(sB + boff, b0, b1, b2, b3);
#pragma unroll
                    for (int mt = 0; mt < 4; mt++) {
                        mma_f16(acc[mt][2*np],   af[mt], b0, b1);
                        mma_f16(acc[mt][2*np+1], af[mt], b2, b3);
                    }
                }
            }
            stage++; if (stage >= 3) stage -= 3;
        }
        cp_wait<0>();               // drain tail empty group

#pragma unroll
        for (int mt = 0; mt < 4; mt++) {
            const int r0 = bm + wm + mt * 16 + (lane >> 2);
#pragma unroll
            for (int nt = 0; nt < 8; nt++) {
                const int col = bn + wn + nt * 8 + ((lane & 3) << 1);
                const float2 bv = *(const float2*)&bias[col];
                float v0 = acc[mt][nt][0] + bv.x, v1 = acc[mt][nt][1] + bv.y;
                float v2 = acc[mt][nt][2] + bv.x, v3 = acc[mt][nt][3] + bv.y;
                if (Ch) {
                    *(uint32_t*)(Ch + (size_t)r0       * N + col) = pkh(v0, v1);
                    *(uint32_t*)(Ch + (size_t)(r0 + 8) * N + col) = pkh(v2, v3);
                } else {
                    *(float2*)&C[(size_t)r0       * N + col] = make_float2(v0, v1);
                    *(float2*)&C[(size_t)(r0 + 8) * N + col] = make_float2(v2, v3);
                }
            }
        }
    }
}

// ============================================================================
// RoPE on q and k, in place on fp16 qkv.
// ============================================================================
__global__ void rope_f16_kernel(__half* __restrict__ qkv)
{
    int idx = blockIdx.x * blockDim.x + threadIdx.x;      // SEQ*NH*16 total
    if (idx >= SEQ * NH * 16) return;
    const int d = idx & 15;
    const int h = (idx >> 4) & 31;
    const int t = idx >> 9;

    const float freq  = __expf(-(float)d * 0.5756462732485115f); // ln(1e4)/16
    const float theta = (float)t * freq;
    float s, c;
    sincosf(theta, &s, &c);

    size_t base = (size_t)t * QKV_N + h * HD + d;
#pragma unroll
    for (int qk = 0; qk < 2; qk++) {
        const size_t i1 = base + qk * DIMS;
        const size_t i2 = i1 + 16;
        float x1 = __half2float(qkv[i1]);
        float x2 = __half2float(qkv[i2]);
        qkv[i1] = __float2half_rn(x1 * c - x2 * s);
        qkv[i2] = __float2half_rn(x1 * s + x2 * c);
    }
}

// ============================================================================
// Tensor-core flash attention, causal, fp16 single-term, occupancy 2.
// CTA = (head, 128 q-rows), 256 threads = 8 warps x 16 rows.
// Fully-masked (warp-local) key tiles are skipped entirely.
// ============================================================================
#define AP      88                       // halves per smem row (176B pitch)
#define SQH     0
#define STG0    (128*AP)                 // after Q tile
#define STG_SZ  (2*64*AP)                // KH + VH
#define KH_OFF  0
#define VH_OFF  (64*AP)
#define ATT_SMEM ((STG0 + 2*STG_SZ) * 2) // 67584 bytes

// scale * log2(e): exp(scale*(s-m)) == exp2(C2*(s-m))
#define C2EXP (0.11180339887498949f * 1.4426950408889634f)

__global__ __launch_bounds__(256, 2) void attn_f16(
    const __half* __restrict__ qkvh,
    __half* __restrict__ aoh)
{
    extern __shared__ __align__(16) __half smA[];
    const uint32_t sb = smem_u32(smA);
    const int h  = blockIdx.x;
    const int qb = (gridDim.y - 1) - blockIdx.y;   // heavy tiles first
    const int tid = threadIdx.x, lane = tid & 31, w = tid >> 5;
    const int q0 = qb * 128;

    // ---- Q load (128 rows x 10 col-chunks) ----
    {
        const size_t off = (size_t)q0 * QKV_N + h * HD;
#pragma unroll
        for (int it = 0; it < 5; it++) {
            const int idx = it * 256 + tid;       // 1280 chunks
            const int row = idx / 10, col = idx % 10;
            cp16(sb + (SQH + row * AP) * 2 + col * 16,
                 qkvh + off + (size_t)row * QKV_N + col * 8);
        }
    }
    auto loadKV = [&](int kb, int s){
        const size_t koff = (size_t)(kb * 64) * QKV_N + DIMS + h * HD;
        const uint32_t stg = sb + (STG0 + s * STG_SZ) * 2;
#pragma unroll
        for (int it = 0; it < 3; it++) {
            const int idx = it * 256 + tid;       // 640 (row,col) pairs
            if (idx < 640) {
                const int row = idx / 10, col = idx % 10;
                const size_t gk = koff + (size_t)row * QKV_N + col * 8;
                cp16(stg + (KH_OFF + row * AP) * 2 + col * 16, qkvh + gk);
                cp16(stg + (VH_OFF + row * AP) * 2 + col * 16, qkvh + gk + DIMS);
            }
        }
    };

    float of[10][4];
#pragma unroll
    for (int i = 0; i < 10; i++)
#pragma unroll
        for (int j = 0; j < 4; j++) of[i][j] = 0.f;
    float mA = -1e30f, mB = -1e30f, lA = 0.f, lB = 0.f;   // raw-unit maxima

    loadKV(0, 0);
    cp_commit();

    const int a_row  = lane & 15;
    const int a_k    = (lane >> 4) << 3;
    const int b_row  = (lane & 7) + ((lane >> 4) << 3);
    const int b_k    = ((lane >> 3) & 1) << 3;
    const int vk     = (lane & 7) + (((lane >> 3) & 1) << 3);
    const int vd     = (lane >> 4) << 3;
    const int clb    = 2 * (lane & 3);
    const int rl     = w * 16 + (lane >> 2);   // local q row (A); B = +8

    const int ntiles = 2 * qb + 2;
    for (int kb = 0; kb < ntiles; kb++) {
        cp_wait<0>();
        __syncthreads();
        if (kb + 1 < ntiles) { loadKV(kb + 1, (kb + 1) & 1); cp_commit(); }

        // warp-level full-mask skip: all this warp's rows < first key col
        if (kb * 64 > q0 + w * 16 + 15) continue;

        const uint32_t stg = sb + (STG0 + (kb & 1) * STG_SZ) * 2;

        // ---- S = Q K^T (raw units) ----
        float sf[8][4];
#pragma unroll
        for (int i = 0; i < 8; i++)
#pragma unroll
            for (int j = 0; j < 4; j++) sf[i][j] = 0.f;

#pragma unroll
        for (int kc = 0; kc < 5; kc++) {
            uint32_t aq[4];
            const uint32_t aoff = (uint32_t)((w * 16 + a_row) * AP + kc * 16 + a_k) * 2;
            ldm_x4(sb + SQH * 2 + aoff, aq[0], aq[1], aq[2], aq[3]);
#pragma unroll
            for (int bp = 0; bp < 4; bp++) {
                const uint32_t boff = (uint32_t)((bp * 16 + b_row) * AP + kc * 16 + b_k) * 2;
                uint32_t b0, b1, b2, b3;
                ldm_x4(stg + KH_OFF * 2 + boff, b0, b1, b2, b3);
                mma_f16(sf[2*bp],   aq, b0, b1);
                mma_f16(sf[2*bp+1], aq, b2, b3);
            }
        }

        // ---- causal mask (raw units) ----
        const bool needmask = (kb * 64 + 63 > q0 + w * 16);
        if (needmask) {
#pragma unroll
            for (int nt = 0; nt < 8; nt++) {
                const int c0 = kb * 64 + nt * 8 + clb;
                const int grA = q0 + rl, grB = grA + 8;
#pragma unroll
                for (int j = 0; j < 2; j++) {
                    if (c0 + j > grA) sf[nt][j]     = -1e30f;
                    if (c0 + j > grB) sf[nt][2 + j] = -1e30f;
                }
            }
        }

        // ---- online softmax: raw max + exp2 with folded constant ----
        float mxA = -1e30f, mxB = -1e30f;
#pragma unroll
        for (int nt = 0; nt < 8; nt++) {
            mxA = fmaxf(mxA, fmaxf(sf[nt][0], sf[nt][1]));
            mxB = fmaxf(mxB, fmaxf(sf[nt][2], sf[nt][3]));
        }
        mxA = fmaxf(mxA, __shfl_xor_sync(0xffffffffu, mxA, 1));
        mxA = fmaxf(mxA, __shfl_xor_sync(0xffffffffu, mxA, 2));
        mxB = fmaxf(mxB, __shfl_xor_sync(0xffffffffu, mxB, 1));
        mxB = fmaxf(mxB, __shfl_xor_sync(0xffffffffu, mxB, 2));
        const float mnA = fmaxf(mA, mxA), mnB = fmaxf(mB, mxB);
        const float alphaA = exp2f((mA - mnA) * C2EXP);
        const float alphaB = exp2f((mB - mnB) * C2EXP);
        mA = mnA; mB = mnB;
        const float cA = -mnA * C2EXP, cB = -mnB * C2EXP;

        float sA = 0.f, sB = 0.f;
#pragma unroll
        for (int nt = 0; nt < 8; nt++) {
#pragma unroll
            for (int j = 0; j < 2; j++) {
                float pA = exp2f(fmaf(sf[nt][j],     C2EXP, cA));
                float pB = exp2f(fmaf(sf[nt][2 + j], C2EXP, cB));
                sf[nt][j] = pA; sf[nt][2 + j] = pB;
                sA += pA; sB += pB;
            }
        }
        sA += __shfl_xor_sync(0xffffffffu, sA, 1);
        sA += __shfl_xor_sync(0xffffffffu, sA, 2);
        sB += __shfl_xor_sync(0xffffffffu, sB, 1);
        sB += __shfl_xor_sync(0xffffffffu, sB, 2);
        lA = lA * alphaA + sA;
        lB = lB * alphaB + sB;
#pragma unroll
        for (int d = 0; d < 10; d++) {
            of[d][0] *= alphaA; of[d][1] *= alphaA;
            of[d][2] *= alphaB; of[d][3] *= alphaB;
        }

        // ---- O += P V, P packed to fp16 in registers ----
#pragma unroll
        for (int kc2 = 0; kc2 < 4; kc2++) {
            uint32_t aP[4];
#pragma unroll
            for (int half = 0; half < 2; half++) {
                const int nt = 2 * kc2 + half;
                aP[half * 2 + 0] = pkh(sf[nt][0], sf[nt][1]);
                aP[half * 2 + 1] = pkh(sf[nt][2], sf[nt][3]);
            }
#pragma unroll
            for (int dp = 0; dp < 5; dp++) {
                const uint32_t voff = (uint32_t)((kc2 * 16 + vk) * AP + dp * 16 + vd) * 2;
                uint32_t v0, v1, v2, v3;
                ldm_x4_t(stg + VH_OFF * 2 + voff, v0, v1, v2, v3);
                mma_f16(of[2*dp],   aP, v0, v1);
                mma_f16(of[2*dp+1], aP, v2, v3);
            }
        }
    }

    // ---- epilogue: normalize, store fp16 ----
    const float iA = 1.f / lA, iB = 1.f / lB;
    const int gA = q0 + w * 16 + (lane >> 2);
    const int colb = h * HD + clb;
#pragma unroll
    for (int nt = 0; nt < 10; nt++) {
        const int col = colb + nt * 8;
        *(uint32_t*)(aoh + (size_t)gA * DIMS + col)       =
            pkh(of[nt][0] * iA, of[nt][1] * iA);
        *(uint32_t*)(aoh + (size_t)(gA + 8) * DIMS + col) =
            pkh(of[nt][2] * iB, of[nt][3] * iB);
    }
}

// ============================================================================
extern "C" void kernel_launch(void* const* d_in, const int* in_sizes, int n_in,
                              void* d_out, int out_size)
{
    const float* x       = (const float*)d_in[0];
    const float* Wqkv_w  = (const float*)d_in[1];
    const float* Wqkv_b  = (const float*)d_in[2];
    const float* out_w   = (const float*)d_in[3];
    const float* out_b   = (const float*)d_in[4];
    // d_in[5] = mask: causal triu(-1e9), implemented structurally; unused.
    float* outp = (float*)d_out;

    __half *xh, *w1h, *w2h, *aoh, *qkvh;
    cudaGetSymbolAddress((void**)&xh,   g_xh);
    cudaGetSymbolAddress((void**)&w1h,  g_w1h);
    cudaGetSymbolAddress((void**)&w2h,  g_w2h);
    cudaGetSymbolAddress((void**)&aoh,  g_aoh);
    cudaGetSymbolAddress((void**)&qkvh, g_qkvh);

    cudaFuncSetAttribute(gemm_f16,
                         cudaFuncAttributeMaxDynamicSharedMemorySize, GM_SMEM);
    cudaFuncSetAttribute(attn_f16,
                         cudaFuncAttributeMaxDynamicSharedMemorySize, ATT_SMEM);

    // 0) fp16 conversions of x and weights
    {
        int n4 = (SEQ * DIMS) / 4;
        cvt_f16_kernel<<<(n4 + 255) / 256, 256>>>(x, xh, n4);
        n4 = (QKV_N * DIMS) / 4;
        cvt_f16_kernel<<<(n4 + 255) / 256, 256>>>(Wqkv_w, w1h, n4);
        n4 = (DIMS * DIMS) / 4;
        cvt_f16_kernel<<<(n4 + 255) / 256, 256>>>(out_w, w2h, n4);
    }
    // 1) QKV projection -> fp16 qkv directly (persistent tiles)
    {
        gemm_f16<<<GEMM_CTAS, 128, GM_SMEM>>>(xh, w1h, Wqkv_b, nullptr, qkvh,
                                              SEQ, QKV_N, DIMS);
    }
    // 2) RoPE on q,k (in place, fp16)
    {
        int total = SEQ * NH * 16;
        rope_f16_kernel<<<(total + 255) / 256, 256>>>(qkvh);
    }
    // 3) tensor-core causal flash attention -> fp16 attn out
    {
        dim3 grid(NH, SEQ / 128);
        attn_f16<<<grid, 256, ATT_SMEM>>>(qkvh, aoh);
    }
    // 4) output projection -> fp32 final output (persistent tiles)
    {
        gemm_f16<<<GEMM_CTAS, 128, GM_SMEM>>>(aoh, w2h, out_b, outp, nullptr,
                                              SEQ, DIMS, DIMS);
    }
}